// round 10
// baseline (speedup 1.0000x reference)
#include <cuda_runtime.h>
#include <cuda_bf16.h>
#include <cstdint>

#define CH 512
#define HW 4096
#define BATCH 2
#define NG 32
#define CPG 16
#define EPSV 1e-6f

typedef __nv_bfloat16 bf16;

// Scratch (allocation-free rule: __device__ globals)
__device__ float g_hn [BATCH * CH * HW];
__device__ bf16  g_hnt[BATCH * CH * HW];                 // [HW, C]
__device__ bf16  g_qk [BATCH * HW * 2 * CH];             // [HW, 1024] q|k
__device__ bf16  g_v  [BATCH * CH * HW];                 // [C, HW]
__device__ bf16  g_aot[BATCH * CH * HW];                 // [HW, C]
__device__ float g_s  [(size_t)BATCH * HW * HW];         // fp32 scores
__device__ bf16  g_attn[(size_t)BATCH * HW * HW];        // bf16 attn
__device__ bf16  g_wb [4 * CH * CH];                     // bf16 weights q,k,v,o
__device__ float g_b2 [2 * CH];                          // bias concat bq|bk

// ---------------------------------------------------------------------------
// helpers
// ---------------------------------------------------------------------------
__device__ __forceinline__ uint32_t smem_u32(const void* p) {
    uint32_t a;
    asm("{ .reg .u64 t; cvta.to.shared.u64 t, %1; cvt.u32.u64 %0, t; }"
        : "=r"(a) : "l"(p));
    return a;
}
__device__ __forceinline__ uint32_t pack_bf2(float a, float b) {
    __nv_bfloat162 h = __floats2bfloat162_rn(a, b);
    return *(uint32_t*)&h;
}
#define CP_ASYNC16(saddr, gaddr) \
    asm volatile("cp.async.cg.shared.global [%0], [%1], 16;" \
                 :: "r"(saddr), "l"(gaddr) : "memory")
#define CP_COMMIT() asm volatile("cp.async.commit_group;" ::: "memory")
#define CP_WAIT0()  asm volatile("cp.async.wait_group 0;"  ::: "memory")
#define CP_WAIT1()  asm volatile("cp.async.wait_group 1;"  ::: "memory")

#define LDSM4(r0, r1, r2, r3, addr) \
    asm volatile("ldmatrix.sync.aligned.m8n8.x4.shared.b16 {%0,%1,%2,%3}, [%4];" \
                 : "=r"(r0), "=r"(r1), "=r"(r2), "=r"(r3) : "r"(addr))

__device__ __forceinline__ void mma16(float (&d)[4], const uint32_t (&a)[4],
                                      const uint32_t (&b)[2]) {
    asm volatile(
        "mma.sync.aligned.m16n8k16.row.col.f32.bf16.bf16.f32 "
        "{%0,%1,%2,%3}, {%4,%5,%6,%7}, {%8,%9}, {%0,%1,%2,%3};"
        : "+f"(d[0]), "+f"(d[1]), "+f"(d[2]), "+f"(d[3])
        : "r"(a[0]), "r"(a[1]), "r"(a[2]), "r"(a[3]), "r"(b[0]), "r"(b[1]));
}

// ---------------------------------------------------------------------------
// Pre-convert weights to bf16 (q,k,v,o) and concat bq|bk
// ---------------------------------------------------------------------------
__global__ __launch_bounds__(256) void prep_kernel(
    const float* __restrict__ w0, const float* __restrict__ w1,
    const float* __restrict__ w2, const float* __restrict__ w3,
    const float* __restrict__ bq, const float* __restrict__ bk,
    bf16* __restrict__ out, float* __restrict__ b2)
{
    const int n4 = CH * CH / 4;
    const int gid = blockIdx.x * 256 + threadIdx.x;
    const int stride = gridDim.x * 256;
    for (int i = gid; i < 4 * n4; i += stride) {
        const int m = i / n4, j = i - m * n4;
        const float* src = (m == 0) ? w0 : (m == 1) ? w1 : (m == 2) ? w2 : w3;
        float4 v = ((const float4*)src)[j];
        uint2 w;
        w.x = pack_bf2(v.x, v.y);
        w.y = pack_bf2(v.z, v.w);
        ((uint2*)out)[i] = w;
    }
    for (int i = gid; i < 2 * CH; i += stride)
        b2[i] = (i < CH) ? bq[i] : bk[i - CH];
}

// ---------------------------------------------------------------------------
// GroupNorm: one block per (group, batch)
// ---------------------------------------------------------------------------
__global__ __launch_bounds__(256) void groupnorm_kernel(
    const float* __restrict__ x, const float* __restrict__ gamma,
    const float* __restrict__ beta, float* __restrict__ out)
{
    const int g = blockIdx.x;
    const int b = blockIdx.y;
    const size_t base = ((size_t)b * CH + g * CPG) * HW;
    const float* xg = x + base;

    float s = 0.f, ss = 0.f;
    for (int i = threadIdx.x; i < CPG * HW; i += 256) {
        float v = xg[i];
        s += v; ss += v * v;
    }
    for (int o = 16; o; o >>= 1) {
        s  += __shfl_xor_sync(0xffffffffu, s,  o);
        ss += __shfl_xor_sync(0xffffffffu, ss, o);
    }
    __shared__ float sw[8], sw2[8];
    const int warp = threadIdx.x >> 5, lane = threadIdx.x & 31;
    if (lane == 0) { sw[warp] = s; sw2[warp] = ss; }
    __syncthreads();
    if (warp == 0) {
        s  = (lane < 8) ? sw[lane]  : 0.f;
        ss = (lane < 8) ? sw2[lane] : 0.f;
        for (int o = 4; o; o >>= 1) {
            s  += __shfl_xor_sync(0xffffffffu, s,  o);
            ss += __shfl_xor_sync(0xffffffffu, ss, o);
        }
        if (lane == 0) {
            const float n    = (float)(CPG * HW);
            const float mean = s / n;
            const float var  = ss / n - mean * mean;
            sw[0]  = mean;
            sw2[0] = rsqrtf(var + EPSV);
        }
    }
    __syncthreads();
    const float mean = sw[0], inv = sw2[0];
    for (int i = threadIdx.x; i < CPG * HW; i += 256) {
        const int c = g * CPG + (i >> 12);
        out[base + i] = (xg[i] - mean) * inv * gamma[c] + beta[c];
    }
}

// ---------------------------------------------------------------------------
// Transpose [C, HW] fp32 -> [HW, C] bf16 per batch
// ---------------------------------------------------------------------------
__global__ __launch_bounds__(256) void transpose_kernel(
    const float* __restrict__ in, bf16* __restrict__ out)
{
    __shared__ float tile[32][33];
    const int b = blockIdx.z;
    in  += (size_t)b * CH * HW;
    out += (size_t)b * CH * HW;
    const int p0 = blockIdx.x * 32, c0 = blockIdx.y * 32;
    const int tx = threadIdx.x & 31, ty = threadIdx.x >> 5;
#pragma unroll
    for (int i = 0; i < 32; i += 8)
        tile[ty + i][tx] = in[(size_t)(c0 + ty + i) * HW + p0 + tx];
    __syncthreads();
#pragma unroll
    for (int i = 0; i < 32; i += 8)
        out[(size_t)(p0 + ty + i) * CH + c0 + tx] =
            __float2bfloat16_rn(tile[tx][ty + i]);
}

// ---------------------------------------------------------------------------
// bf16 mma.sync GEMM: D = scale * A(M,K) . B(N,K)^T  (+epilogue)
// MODE: 0=scale only, 1=+bias[n], 2=+bias[m], 3=+bias[m]+res[m,n]
// OT:   0 -> fp32 output, 1 -> bf16 output
// CTA tile 128m x 256n, BK=32, 3-stage cp.async, 256 threads (8 warps),
// warp grid 2m x 4n, warp tile 64x64 (32 MMAs per k16 step).
// smem row stride 80B: conflict-free for cp.async stores and ldmatrix.
// ---------------------------------------------------------------------------
#define STG_A 10240          // 128 rows * 80 B
#define STG_B 20480          // 256 rows * 80 B
#define STG_T (STG_A + STG_B)
template<int MODE, int OT>
__global__ __launch_bounds__(256) void bgemm(
    const bf16* __restrict__ A, const bf16* __restrict__ B,
    void* __restrict__ Cv,
    const float* __restrict__ bias, const float* __restrict__ res,
    int K, int lda, int ldb, int ldc,
    long long sA, long long sB, long long sC, float scale)
{
    extern __shared__ char sm[];
    const uint32_t Abase = smem_u32(sm);            // 3 stages of A
    const uint32_t Bbase = Abase + 3 * STG_A;       // 3 stages of B

    const int tid = threadIdx.x, lane = tid & 31, wid = tid >> 5;
    const int wm = wid & 1, wn = wid >> 1;          // warp grid 2m x 4n
    const int grp = lane >> 2, tig = lane & 3;
    const int bz = blockIdx.z;
    A += bz * sA; B += bz * sB;
    const float* resb = (MODE == 3) ? res + bz * sC : nullptr;
    const int m0 = blockIdx.y * 128, n0 = blockIdx.x * 256;

    // cp.async mapping: lr = tid>>2 (0..63), chunk = (tid&3)*16B
    // A rows lr, lr+64;  B rows lr, +64, +128, +192   (6 cp.async / thread)
    const int lr = tid >> 2;
    const int lc8 = (tid & 3) * 8;                  // bf16 col offset
    const bf16* Ag0 = A + (size_t)(m0 + lr) * lda + lc8;
    const bf16* Ag1 = Ag0 + (size_t)64 * lda;
    const bf16* Bg0 = B + (size_t)(n0 + lr) * ldb + lc8;
    const uint32_t sa0 = Abase + (uint32_t)(lr * 80 + (tid & 3) * 16);
    const uint32_t sb0 = Bbase + (uint32_t)(lr * 80 + (tid & 3) * 16);
    const uint32_t r64 = 64 * 80;

    // ldmatrix lane addresses:
    // A: 4 slabs of 16 rows (m16 tiles)
    const uint32_t la_row = lane & 15, la_k = (lane >> 4) * 16;
    uint32_t aaddr[4];
#pragma unroll
    for (int mt = 0; mt < 4; mt++)
        aaddr[mt] = Abase + (uint32_t)((wm * 64 + mt * 16 + la_row) * 80) + la_k;
    // B: 4 slabs of 16 rows, each = 2 n8 tiles
    const uint32_t lb_row = ((lane >> 4) * 8) + (lane & 7);
    const uint32_t lb_k = ((lane >> 3) & 1) * 16;
    uint32_t baddr[4];
#pragma unroll
    for (int h = 0; h < 4; h++)
        baddr[h] = Bbase + (uint32_t)((wn * 64 + h * 16 + lb_row) * 80) + lb_k;

    float acc[4][8][4];
#pragma unroll
    for (int mt = 0; mt < 4; mt++)
#pragma unroll
        for (int nt = 0; nt < 8; nt++)
#pragma unroll
            for (int j = 0; j < 4; j++) acc[mt][nt][j] = 0.f;

    const int T = K >> 5;           // BK=32

    // prologue: stages 0,1
#pragma unroll
    for (int p = 0; p < 2; p++) {
        const size_t ko = (size_t)p * 32;
        const uint32_t stA = p * STG_A, stB = p * STG_B;
        CP_ASYNC16(sa0 + stA,       Ag0 + ko);
        CP_ASYNC16(sa0 + stA + r64, Ag1 + ko);
#pragma unroll
        for (int h = 0; h < 4; h++)
            CP_ASYNC16(sb0 + stB + h * r64, Bg0 + (size_t)h * 64 * ldb + ko);
        CP_COMMIT();
    }

    int cur = 0, nxt_issue = 2;
    for (int kt = 0; kt < T; kt++) {
        if (kt + 1 < T) CP_WAIT1(); else CP_WAIT0();
        __syncthreads();

        const uint32_t sgA = cur * STG_A, sgB = cur * STG_B;
#pragma unroll
        for (int kk = 0; kk < 2; kk++) {          // two k16 steps per tile
            const uint32_t ko = kk * 32;          // 16 bf16 = 32 bytes
            uint32_t af[4][4], bf[8][2];
#pragma unroll
            for (int mt = 0; mt < 4; mt++)
                LDSM4(af[mt][0], af[mt][1], af[mt][2], af[mt][3],
                      aaddr[mt] + sgA + ko);
#pragma unroll
            for (int h = 0; h < 4; h++)
                LDSM4(bf[2*h][0], bf[2*h][1], bf[2*h+1][0], bf[2*h+1][1],
                      baddr[h] + sgB + ko);
#pragma unroll
            for (int mt = 0; mt < 4; mt++)
#pragma unroll
                for (int nt = 0; nt < 8; nt++)
                    mma16(acc[mt][nt], af[mt], bf[nt]);
        }

        if (kt + 2 < T) {
            const size_t ko = (size_t)(kt + 2) * 32;
            const uint32_t stA = nxt_issue * STG_A, stB = nxt_issue * STG_B;
            CP_ASYNC16(sa0 + stA,       Ag0 + ko);
            CP_ASYNC16(sa0 + stA + r64, Ag1 + ko);
#pragma unroll
            for (int h = 0; h < 4; h++)
                CP_ASYNC16(sb0 + stB + h * r64, Bg0 + (size_t)h * 64 * ldb + ko);
            CP_COMMIT();
        }
        cur = (cur + 1 == 3) ? 0 : cur + 1;
        nxt_issue = (nxt_issue + 1 == 3) ? 0 : nxt_issue + 1;
    }

    // Epilogue
    float* Cf = (float*)Cv + ((OT == 0) ? bz * sC : 0);
    bf16*  Cb = (bf16*)Cv  + ((OT == 1) ? bz * sC : 0);
#pragma unroll
    for (int mt = 0; mt < 4; mt++) {
        const int r0 = m0 + wm * 64 + mt * 16 + grp;
        float bm0 = 0.f, bm1 = 0.f;
        if (MODE == 2 || MODE == 3) { bm0 = bias[r0]; bm1 = bias[r0 + 8]; }
#pragma unroll
        for (int nt = 0; nt < 8; nt++) {
            const int c = n0 + wn * 64 + nt * 8 + tig * 2;
            const float* d = acc[mt][nt];
            float2 o0 = { d[0] * scale, d[1] * scale };
            float2 o1 = { d[2] * scale, d[3] * scale };
            if (MODE == 1) {
                const float2 bn = *(const float2*)&bias[c];
                o0.x += bn.x; o0.y += bn.y; o1.x += bn.x; o1.y += bn.y;
            }
            if (MODE == 2 || MODE == 3) {
                o0.x += bm0; o0.y += bm0; o1.x += bm1; o1.y += bm1;
            }
            const size_t i0 = (size_t)r0 * ldc + c;
            const size_t i1 = (size_t)(r0 + 8) * ldc + c;
            if (MODE == 3) {
                const float2 r0v = *(const float2*)&resb[i0];
                const float2 r1v = *(const float2*)&resb[i1];
                o0.x += r0v.x; o0.y += r0v.y; o1.x += r1v.x; o1.y += r1v.y;
            }
            if (OT == 0) {
                *(float2*)&Cf[i0] = o0;
                *(float2*)&Cf[i1] = o1;
            } else {
                *(uint32_t*)&Cb[i0] = pack_bf2(o0.x, o0.y);
                *(uint32_t*)&Cb[i1] = pack_bf2(o1.x, o1.y);
            }
        }
    }
}

// ---------------------------------------------------------------------------
// Row softmax: fp32 scores in -> bf16 attn out
// ---------------------------------------------------------------------------
__global__ __launch_bounds__(256) void softmax_kernel(
    const float* __restrict__ s, bf16* __restrict__ attn)
{
    const float4* p = (const float4*)(s + (size_t)blockIdx.x * HW);
    uint2* po = (uint2*)(attn + (size_t)blockIdx.x * HW);
    const int t = threadIdx.x;
    const int warp = t >> 5, lane = t & 31;
    __shared__ float sh[8];

    float4 v[4];
    float mx = -3.4e38f;
#pragma unroll
    for (int i = 0; i < 4; i++) {
        v[i] = p[t + i * 256];
        mx = fmaxf(mx, fmaxf(fmaxf(v[i].x, v[i].y), fmaxf(v[i].z, v[i].w)));
    }
    for (int o = 16; o; o >>= 1) mx = fmaxf(mx, __shfl_xor_sync(0xffffffffu, mx, o));
    if (lane == 0) sh[warp] = mx;
    __syncthreads();
    if (warp == 0) {
        float m = (lane < 8) ? sh[lane] : -3.4e38f;
        for (int o = 4; o; o >>= 1) m = fmaxf(m, __shfl_xor_sync(0xffffffffu, m, o));
        if (lane == 0) sh[0] = m;
    }
    __syncthreads();
    mx = sh[0];
    __syncthreads();

    float sum = 0.f;
#pragma unroll
    for (int i = 0; i < 4; i++) {
        v[i].x = __expf(v[i].x - mx);
        v[i].y = __expf(v[i].y - mx);
        v[i].z = __expf(v[i].z - mx);
        v[i].w = __expf(v[i].w - mx);
        sum += v[i].x + v[i].y + v[i].z + v[i].w;
    }
    for (int o = 16; o; o >>= 1) sum += __shfl_xor_sync(0xffffffffu, sum, o);
    if (lane == 0) sh[warp] = sum;
    __syncthreads();
    if (warp == 0) {
        float m = (lane < 8) ? sh[lane] : 0.f;
        for (int o = 4; o; o >>= 1) m += __shfl_xor_sync(0xffffffffu, m, o);
        if (lane == 0) sh[0] = m;
    }
    __syncthreads();
    const float inv = 1.0f / sh[0];
#pragma unroll
    for (int i = 0; i < 4; i++) {
        uint2 w;
        w.x = pack_bf2(v[i].x * inv, v[i].y * inv);
        w.y = pack_bf2(v[i].z * inv, v[i].w * inv);
        po[t + i * 256] = w;
    }
}

// ---------------------------------------------------------------------------
extern "C" void kernel_launch(void* const* d_in, const int* in_sizes, int n_in,
                              void* d_out, int out_size)
{
    const float* x     = (const float*)d_in[0];
    const float* gamma = (const float*)d_in[1];
    const float* beta  = (const float*)d_in[2];
    const float* wq    = (const float*)d_in[3];
    const float* bq    = (const float*)d_in[4];
    const float* wk    = (const float*)d_in[5];
    const float* bk    = (const float*)d_in[6];
    const float* wv    = (const float*)d_in[7];
    const float* bv    = (const float*)d_in[8];
    const float* wo    = (const float*)d_in[9];
    const float* bo    = (const float*)d_in[10];
    float* out = (float*)d_out;

    float *hn, *s, *b2;
    bf16 *hnt, *qk, *v, *aot, *attn, *wb;
    cudaGetSymbolAddress((void**)&hn,   g_hn);
    cudaGetSymbolAddress((void**)&hnt,  g_hnt);
    cudaGetSymbolAddress((void**)&qk,   g_qk);
    cudaGetSymbolAddress((void**)&v,    g_v);
    cudaGetSymbolAddress((void**)&aot,  g_aot);
    cudaGetSymbolAddress((void**)&s,    g_s);
    cudaGetSymbolAddress((void**)&attn, g_attn);
    cudaGetSymbolAddress((void**)&wb,   g_wb);
    cudaGetSymbolAddress((void**)&b2,   g_b2);
    const bf16* wvb = wb + 2 * CH * CH;
    const bf16* wob = wb + 3 * CH * CH;

    const int SMEM = 3 * STG_T;       // 92160 B
    static int smem_set = 0;
    if (!smem_set) {
        cudaFuncSetAttribute(bgemm<1,1>, cudaFuncAttributeMaxDynamicSharedMemorySize, SMEM);
        cudaFuncSetAttribute(bgemm<2,1>, cudaFuncAttributeMaxDynamicSharedMemorySize, SMEM);
        cudaFuncSetAttribute(bgemm<0,0>, cudaFuncAttributeMaxDynamicSharedMemorySize, SMEM);
        cudaFuncSetAttribute(bgemm<0,1>, cudaFuncAttributeMaxDynamicSharedMemorySize, SMEM);
        cudaFuncSetAttribute(bgemm<3,0>, cudaFuncAttributeMaxDynamicSharedMemorySize, SMEM);
        smem_set = 1;
    }

    const long long sCH  = (long long)CH * HW;
    const long long sQK  = (long long)HW * 2 * CH;
    const long long sHW  = (long long)HW * HW;
    const float scale = 0.044194173824159216f;   // 1/sqrt(512)

    // 0. weights -> bf16, bias concat
    prep_kernel<<<256, 256>>>(wq, wk, wv, wo, bq, bk, wb, b2);
    // 1. GroupNorm -> hn [C, HW] fp32
    groupnorm_kernel<<<dim3(NG, BATCH), 256>>>(x, gamma, beta, hn);
    // 2. hn -> hnt [HW, C] bf16
    transpose_kernel<<<dim3(HW / 32, CH / 32, BATCH), 256>>>(hn, hnt);

    // 3. qk[p, 0:1024] = hnt . [Wq;Wk]^T + [bq;bk]   (M=4096, N=1024, K=512)
    bgemm<1,1><<<dim3(2 * CH / 256, HW / 128, BATCH), 256, SMEM>>>(
        hnt, wb, qk, b2, nullptr, CH, CH, CH, 2 * CH, sCH, 0, sQK, 1.f);
    // 4. v[c,p] = Wv . hnt^T + bv[c]                 (M=512, N=4096, K=512)
    bgemm<2,1><<<dim3(HW / 256, CH / 128, BATCH), 256, SMEM>>>(
        wvb, hnt, v, bv, nullptr, CH, CH, CH, HW, 0, sCH, sCH, 1.f);

    // 5. s[i,j] = (q . k^T) * scale                  (M=4096, N=4096, K=512)
    bgemm<0,0><<<dim3(HW / 256, HW / 128, BATCH), 256, SMEM>>>(
        qk, qk + CH, s, nullptr, nullptr, CH, 2 * CH, 2 * CH, HW, sQK, sQK, sHW, scale);

    // 6. softmax rows -> bf16 attn
    softmax_kernel<<<BATCH * HW, 256>>>(s, attn);

    // 7. ao_t[i,c] = attn . v^T                      (M=4096, N=512, K=4096)
    bgemm<0,1><<<dim3(CH / 256, HW / 128, BATCH), 256, SMEM>>>(
        attn, v, aot, nullptr, nullptr, HW, HW, HW, CH, sHW, sCH, sCH, 1.f);

    // 8. out[o,p] = Wo . ao_t^T + bo[o] + x          (M=512, N=4096, K=512)
    bgemm<3,0><<<dim3(HW / 256, CH / 128, BATCH), 256, SMEM>>>(
        wob, aot, out, bo, x, CH, CH, CH, HW, 0, sCH, sCH, 1.f);
}

// round 11
// speedup vs baseline: 1.1222x; 1.1222x over previous
#include <cuda_runtime.h>
#include <cuda_bf16.h>
#include <cstdint>

#define CH 512
#define HW 4096
#define BATCH 2
#define NG 32
#define CPG 16
#define EPSV 1e-6f

typedef __nv_bfloat16 bf16;

// Scratch (allocation-free rule: __device__ globals)
__device__ bf16   g_hnt[BATCH * CH * HW];                 // [HW, C]
__device__ bf16   g_qk [BATCH * HW * 2 * CH];             // [HW, 1024] q|k
__device__ bf16   g_v  [BATCH * CH * HW];                 // [C, HW]
__device__ bf16   g_aot[BATCH * CH * HW];                 // [HW, C]
__device__ float  g_s  [(size_t)BATCH * HW * HW];         // fp32 scores
__device__ bf16   g_attn[(size_t)BATCH * HW * HW];        // bf16 attn
__device__ bf16   g_wb [4 * CH * CH];                     // bf16 weights q,k,v,o
__device__ float  g_b2 [2 * CH];                          // bias concat bq|bk
__device__ float2 g_stats[BATCH * NG];                    // {mean, inv} per group

// ---------------------------------------------------------------------------
// helpers
// ---------------------------------------------------------------------------
__device__ __forceinline__ uint32_t smem_u32(const void* p) {
    uint32_t a;
    asm("{ .reg .u64 t; cvta.to.shared.u64 t, %1; cvt.u32.u64 %0, t; }"
        : "=r"(a) : "l"(p));
    return a;
}
__device__ __forceinline__ uint32_t pack_bf2(float a, float b) {
    __nv_bfloat162 h = __floats2bfloat162_rn(a, b);
    return *(uint32_t*)&h;
}
#define CP_ASYNC16(saddr, gaddr) \
    asm volatile("cp.async.cg.shared.global [%0], [%1], 16;" \
                 :: "r"(saddr), "l"(gaddr) : "memory")
#define CP_COMMIT() asm volatile("cp.async.commit_group;" ::: "memory")
#define CP_WAIT0()  asm volatile("cp.async.wait_group 0;"  ::: "memory")
#define CP_WAIT1()  asm volatile("cp.async.wait_group 1;"  ::: "memory")

#define LDSM4(r0, r1, r2, r3, addr) \
    asm volatile("ldmatrix.sync.aligned.m8n8.x4.shared.b16 {%0,%1,%2,%3}, [%4];" \
                 : "=r"(r0), "=r"(r1), "=r"(r2), "=r"(r3) : "r"(addr))

__device__ __forceinline__ void mma16(float (&d)[4], const uint32_t (&a)[4],
                                      const uint32_t (&b)[2]) {
    asm volatile(
        "mma.sync.aligned.m16n8k16.row.col.f32.bf16.bf16.f32 "
        "{%0,%1,%2,%3}, {%4,%5,%6,%7}, {%8,%9}, {%0,%1,%2,%3};"
        : "+f"(d[0]), "+f"(d[1]), "+f"(d[2]), "+f"(d[3])
        : "r"(a[0]), "r"(a[1]), "r"(a[2]), "r"(a[3]), "r"(b[0]), "r"(b[1]));
}

// load one k16-step fragment set for the warp (4 A slabs + 2 B slabs)
__device__ __forceinline__ void ldsm_set(uint32_t a0, uint32_t b0, uint32_t off,
                                         uint32_t (&af)[4][4], uint32_t (&bf)[4][2]) {
#pragma unroll
    for (int mt = 0; mt < 4; mt++)
        LDSM4(af[mt][0], af[mt][1], af[mt][2], af[mt][3], a0 + mt * 1280 + off);
#pragma unroll
    for (int h = 0; h < 2; h++)
        LDSM4(bf[2*h][0], bf[2*h][1], bf[2*h+1][0], bf[2*h+1][1],
              b0 + h * 1280 + off);
}
__device__ __forceinline__ void mma_all(float (&acc)[4][4][4],
                                        const uint32_t (&af)[4][4],
                                        const uint32_t (&bf)[4][2]) {
#pragma unroll
    for (int mt = 0; mt < 4; mt++)
#pragma unroll
        for (int nt = 0; nt < 4; nt++)
            mma16(acc[mt][nt], af[mt], bf[nt]);
}

// ---------------------------------------------------------------------------
// Pre-convert weights to bf16 (q,k,v,o) and concat bq|bk
// ---------------------------------------------------------------------------
__global__ __launch_bounds__(256) void prep_kernel(
    const float* __restrict__ w0, const float* __restrict__ w1,
    const float* __restrict__ w2, const float* __restrict__ w3,
    const float* __restrict__ bq, const float* __restrict__ bk,
    bf16* __restrict__ out, float* __restrict__ b2)
{
    const int n4 = CH * CH / 4;
    const int gid = blockIdx.x * 256 + threadIdx.x;
    const int stride = gridDim.x * 256;
    for (int i = gid; i < 4 * n4; i += stride) {
        const int m = i / n4, j = i - m * n4;
        const float* src = (m == 0) ? w0 : (m == 1) ? w1 : (m == 2) ? w2 : w3;
        float4 v = ((const float4*)src)[j];
        uint2 w;
        w.x = pack_bf2(v.x, v.y);
        w.y = pack_bf2(v.z, v.w);
        ((uint2*)out)[i] = w;
    }
    for (int i = gid; i < 2 * CH; i += stride)
        b2[i] = (i < CH) ? bq[i] : bk[i - CH];
}

// ---------------------------------------------------------------------------
// GroupNorm stats: one block per (group, batch) -> {mean, rsqrt(var+eps)}
// ---------------------------------------------------------------------------
__global__ __launch_bounds__(256) void gn_stats_kernel(
    const float* __restrict__ x, float2* __restrict__ stats)
{
    const int g = blockIdx.x;
    const int b = blockIdx.y;
    const size_t base = ((size_t)b * CH + g * CPG) * HW;
    const float* xg = x + base;

    float s = 0.f, ss = 0.f;
    for (int i = threadIdx.x; i < CPG * HW; i += 256) {
        float v = xg[i];
        s += v; ss += v * v;
    }
    for (int o = 16; o; o >>= 1) {
        s  += __shfl_xor_sync(0xffffffffu, s,  o);
        ss += __shfl_xor_sync(0xffffffffu, ss, o);
    }
    __shared__ float sw[8], sw2[8];
    const int warp = threadIdx.x >> 5, lane = threadIdx.x & 31;
    if (lane == 0) { sw[warp] = s; sw2[warp] = ss; }
    __syncthreads();
    if (warp == 0) {
        s  = (lane < 8) ? sw[lane]  : 0.f;
        ss = (lane < 8) ? sw2[lane] : 0.f;
        for (int o = 4; o; o >>= 1) {
            s  += __shfl_xor_sync(0xffffffffu, s,  o);
            ss += __shfl_xor_sync(0xffffffffu, ss, o);
        }
        if (lane == 0) {
            const float n    = (float)(CPG * HW);
            const float mean = s / n;
            const float var  = ss / n - mean * mean;
            stats[b * NG + g] = make_float2(mean, rsqrtf(var + EPSV));
        }
    }
}

// ---------------------------------------------------------------------------
// Fused GroupNorm-apply + transpose: x [C, HW] fp32 -> hnt [HW, C] bf16
// ---------------------------------------------------------------------------
__global__ __launch_bounds__(256) void gn_apply_transpose(
    const float* __restrict__ x, const float2* __restrict__ stats,
    const float* __restrict__ gamma, const float* __restrict__ beta,
    bf16* __restrict__ out)
{
    __shared__ float tile[32][33];
    const int b = blockIdx.z;
    x   += (size_t)b * CH * HW;
    out += (size_t)b * CH * HW;
    const int p0 = blockIdx.x * 32, c0 = blockIdx.y * 32;
    const int tx = threadIdx.x & 31, ty = threadIdx.x >> 5;
#pragma unroll
    for (int i = 0; i < 32; i += 8)
        tile[ty + i][tx] = x[(size_t)(c0 + ty + i) * HW + p0 + tx];
    __syncthreads();
    const int c = c0 + tx;
    const float2 st = stats[b * NG + (c >> 4)];
    const float sc = st.y * gamma[c];
    const float sh = beta[c] - st.x * sc;
#pragma unroll
    for (int i = 0; i < 32; i += 8)
        out[(size_t)(p0 + ty + i) * CH + c] =
            __float2bfloat16_rn(tile[tx][ty + i] * sc + sh);
}

// ---------------------------------------------------------------------------
// bf16 mma.sync GEMM: D = scale * A(M,K) . B(N,K)^T  (+epilogue)
// MODE: 0=scale only, 1=+bias[n], 2=+bias[m], 3=+bias[m]+res[m,n]
// OT:   0 -> fp32 output, 1 -> bf16 output
// 128x128 CTA tile, BK=32, 3-stage cp.async, 256 threads, warp tile 64x32.
// Software-pipelined frag double-buffer: each warp exits the barrier holding
// the frags for its next MMA block (convoy-free mainloop).
// ---------------------------------------------------------------------------
#define STG_B 10240
template<int MODE, int OT>
__global__ __launch_bounds__(256, 2) void bgemm(
    const bf16* __restrict__ A, const bf16* __restrict__ B,
    void* __restrict__ Cv,
    const float* __restrict__ bias, const float* __restrict__ res,
    int K, int lda, int ldb, int ldc,
    long long sA, long long sB, long long sC, float scale)
{
    extern __shared__ char sm[];
    const uint32_t Abase = smem_u32(sm);
    const uint32_t Bbase = Abase + 3 * STG_B;

    const int tid = threadIdx.x, lane = tid & 31, wid = tid >> 5;
    const int wm = wid & 1, wn = wid >> 1;          // warp grid 2 x 4
    const int grp = lane >> 2, tig = lane & 3;
    const int bz = blockIdx.z;
    A += bz * sA; B += bz * sB;
    const float* resb = (MODE == 3) ? res + bz * sC : nullptr;
    const int m0 = blockIdx.y * 128, n0 = blockIdx.x * 128;

    // cp.async mapping: thread -> rows (tid>>2, +64), 16B chunk (tid&3)
    const int lr = tid >> 2;
    const int lc8 = (tid & 3) * 8;
    const bf16* Ag0 = A + (size_t)(m0 + lr) * lda + lc8;
    const bf16* Ag1 = Ag0 + (size_t)64 * lda;
    const bf16* Bg0 = B + (size_t)(n0 + lr) * ldb + lc8;
    const bf16* Bg1 = Bg0 + (size_t)64 * ldb;
    const uint32_t sa0 = Abase + (uint32_t)(lr * 80 + (tid & 3) * 16);
    const uint32_t sb0 = Bbase + (uint32_t)(lr * 80 + (tid & 3) * 16);
    const uint32_t r64 = 64 * 80;

    // ldmatrix base lane addresses (stage 0, k-step 0)
    const uint32_t la_row = lane & 15, la_k = (lane >> 4) * 16;
    const uint32_t aaddr0 = Abase + (uint32_t)((wm * 64 + la_row) * 80) + la_k;
    const uint32_t lb_row = ((lane >> 4) * 8) + (lane & 7);
    const uint32_t lb_k = ((lane >> 3) & 1) * 16;
    const uint32_t baddr0 = Bbase + (uint32_t)((wn * 32 + lb_row) * 80) + lb_k;

    float acc[4][4][4];
#pragma unroll
    for (int mt = 0; mt < 4; mt++)
#pragma unroll
        for (int nt = 0; nt < 4; nt++)
#pragma unroll
            for (int j = 0; j < 4; j++) acc[mt][nt][j] = 0.f;

    const int T = K >> 5;           // BK=32

    // prologue: stages 0,1
#pragma unroll
    for (int p = 0; p < 2; p++) {
        const size_t ko = (size_t)p * 32;
        CP_ASYNC16(sa0 + p * STG_B,        Ag0 + ko);
        CP_ASYNC16(sa0 + p * STG_B + r64,  Ag1 + ko);
        CP_ASYNC16(sb0 + p * STG_B,        Bg0 + ko);
        CP_ASYNC16(sb0 + p * STG_B + r64,  Bg1 + ko);
        CP_COMMIT();
    }
    CP_WAIT1();                     // stage 0 arrived
    __syncthreads();

    uint32_t af[2][4][4], bfr[2][4][2];
    ldsm_set(aaddr0, baddr0, 0, af[0], bfr[0]);       // stage 0, k-step 0

    int cur = 0, nxt = 2;
    for (int kt = 0; kt < T; kt++) {
        const uint32_t so = cur * STG_B;
        ldsm_set(aaddr0, baddr0, so + 32, af[1], bfr[1]);   // k-step 1
        mma_all(acc, af[0], bfr[0]);

        if (kt + 2 < T) {
            const size_t ko = (size_t)(kt + 2) * 32;
            const uint32_t st = nxt * STG_B;
            CP_ASYNC16(sa0 + st,       Ag0 + ko);
            CP_ASYNC16(sa0 + st + r64, Ag1 + ko);
            CP_ASYNC16(sb0 + st,       Bg0 + ko);
            CP_ASYNC16(sb0 + st + r64, Bg1 + ko);
        }
        CP_COMMIT();

        const int nstage = (cur + 1 == 3) ? 0 : cur + 1;
        if (kt + 1 < T) {
            CP_WAIT1();             // next stage data arrived
            __syncthreads();        // all warps done reading the reuse slot
            ldsm_set(aaddr0, baddr0, nstage * STG_B, af[0], bfr[0]);
        }
        mma_all(acc, af[1], bfr[1]);
        cur = nstage;
        nxt = (nxt + 1 == 3) ? 0 : nxt + 1;
    }

    // Epilogue
    float* Cf = (float*)Cv + ((OT == 0) ? bz * sC : 0);
    bf16*  Cb = (bf16*)Cv  + ((OT == 1) ? bz * sC : 0);
#pragma unroll
    for (int mt = 0; mt < 4; mt++) {
        const int r0 = m0 + wm * 64 + mt * 16 + grp;
        float bm0 = 0.f, bm1 = 0.f;
        if (MODE == 2 || MODE == 3) { bm0 = bias[r0]; bm1 = bias[r0 + 8]; }
#pragma unroll
        for (int nt = 0; nt < 4; nt++) {
            const int c = n0 + wn * 32 + nt * 8 + tig * 2;
            const float* d = acc[mt][nt];
            float2 o0 = { d[0] * scale, d[1] * scale };
            float2 o1 = { d[2] * scale, d[3] * scale };
            if (MODE == 1) {
                const float2 bn = *(const float2*)&bias[c];
                o0.x += bn.x; o0.y += bn.y; o1.x += bn.x; o1.y += bn.y;
            }
            if (MODE == 2 || MODE == 3) {
                o0.x += bm0; o0.y += bm0; o1.x += bm1; o1.y += bm1;
            }
            const size_t i0 = (size_t)r0 * ldc + c;
            const size_t i1 = (size_t)(r0 + 8) * ldc + c;
            if (MODE == 3) {
                const float2 r0v = *(const float2*)&resb[i0];
                const float2 r1v = *(const float2*)&resb[i1];
                o0.x += r0v.x; o0.y += r0v.y; o1.x += r1v.x; o1.y += r1v.y;
            }
            if (OT == 0) {
                *(float2*)&Cf[i0] = o0;
                *(float2*)&Cf[i1] = o1;
            } else {
                *(uint32_t*)&Cb[i0] = pack_bf2(o0.x, o0.y);
                *(uint32_t*)&Cb[i1] = pack_bf2(o1.x, o1.y);
            }
        }
    }
}

// ---------------------------------------------------------------------------
// Row softmax: fp32 scores in -> bf16 attn out
// ---------------------------------------------------------------------------
__global__ __launch_bounds__(256) void softmax_kernel(
    const float* __restrict__ s, bf16* __restrict__ attn)
{
    const float4* p = (const float4*)(s + (size_t)blockIdx.x * HW);
    uint2* po = (uint2*)(attn + (size_t)blockIdx.x * HW);
    const int t = threadIdx.x;
    const int warp = t >> 5, lane = t & 31;
    __shared__ float sh[8];

    float4 v[4];
    float mx = -3.4e38f;
#pragma unroll
    for (int i = 0; i < 4; i++) {
        v[i] = p[t + i * 256];
        mx = fmaxf(mx, fmaxf(fmaxf(v[i].x, v[i].y), fmaxf(v[i].z, v[i].w)));
    }
    for (int o = 16; o; o >>= 1) mx = fmaxf(mx, __shfl_xor_sync(0xffffffffu, mx, o));
    if (lane == 0) sh[warp] = mx;
    __syncthreads();
    if (warp == 0) {
        float m = (lane < 8) ? sh[lane] : -3.4e38f;
        for (int o = 4; o; o >>= 1) m = fmaxf(m, __shfl_xor_sync(0xffffffffu, m, o));
        if (lane == 0) sh[0] = m;
    }
    __syncthreads();
    mx = sh[0];
    __syncthreads();

    float sum = 0.f;
#pragma unroll
    for (int i = 0; i < 4; i++) {
        v[i].x = __expf(v[i].x - mx);
        v[i].y = __expf(v[i].y - mx);
        v[i].z = __expf(v[i].z - mx);
        v[i].w = __expf(v[i].w - mx);
        sum += v[i].x + v[i].y + v[i].z + v[i].w;
    }
    for (int o = 16; o; o >>= 1) sum += __shfl_xor_sync(0xffffffffu, sum, o);
    if (lane == 0) sh[warp] = sum;
    __syncthreads();
    if (warp == 0) {
        float m = (lane < 8) ? sh[lane] : 0.f;
        for (int o = 4; o; o >>= 1) m += __shfl_xor_sync(0xffffffffu, m, o);
        if (lane == 0) sh[0] = m;
    }
    __syncthreads();
    const float inv = 1.0f / sh[0];
#pragma unroll
    for (int i = 0; i < 4; i++) {
        uint2 w;
        w.x = pack_bf2(v[i].x * inv, v[i].y * inv);
        w.y = pack_bf2(v[i].z * inv, v[i].w * inv);
        po[t + i * 256] = w;
    }
}

// ---------------------------------------------------------------------------
extern "C" void kernel_launch(void* const* d_in, const int* in_sizes, int n_in,
                              void* d_out, int out_size)
{
    const float* x     = (const float*)d_in[0];
    const float* gamma = (const float*)d_in[1];
    const float* beta  = (const float*)d_in[2];
    const float* wq    = (const float*)d_in[3];
    const float* bq    = (const float*)d_in[4];
    const float* wk    = (const float*)d_in[5];
    const float* bk    = (const float*)d_in[6];
    const float* wv    = (const float*)d_in[7];
    const float* bv    = (const float*)d_in[8];
    const float* wo    = (const float*)d_in[9];
    const float* bo    = (const float*)d_in[10];
    float* out = (float*)d_out;

    float *s, *b2;
    float2* stats;
    bf16 *hnt, *qk, *v, *aot, *attn, *wb;
    cudaGetSymbolAddress((void**)&hnt,   g_hnt);
    cudaGetSymbolAddress((void**)&qk,    g_qk);
    cudaGetSymbolAddress((void**)&v,     g_v);
    cudaGetSymbolAddress((void**)&aot,   g_aot);
    cudaGetSymbolAddress((void**)&s,     g_s);
    cudaGetSymbolAddress((void**)&attn,  g_attn);
    cudaGetSymbolAddress((void**)&wb,    g_wb);
    cudaGetSymbolAddress((void**)&b2,    g_b2);
    cudaGetSymbolAddress((void**)&stats, g_stats);
    const bf16* wvb = wb + 2 * CH * CH;
    const bf16* wob = wb + 3 * CH * CH;

    const int SMEM = 6 * STG_B;       // 61440 B
    static int smem_set = 0;
    if (!smem_set) {
        cudaFuncSetAttribute(bgemm<1,1>, cudaFuncAttributeMaxDynamicSharedMemorySize, SMEM);
        cudaFuncSetAttribute(bgemm<2,1>, cudaFuncAttributeMaxDynamicSharedMemorySize, SMEM);
        cudaFuncSetAttribute(bgemm<0,0>, cudaFuncAttributeMaxDynamicSharedMemorySize, SMEM);
        cudaFuncSetAttribute(bgemm<0,1>, cudaFuncAttributeMaxDynamicSharedMemorySize, SMEM);
        cudaFuncSetAttribute(bgemm<3,0>, cudaFuncAttributeMaxDynamicSharedMemorySize, SMEM);
        smem_set = 1;
    }

    const long long sCH  = (long long)CH * HW;
    const long long sQK  = (long long)HW * 2 * CH;
    const long long sHW  = (long long)HW * HW;
    const float scale = 0.044194173824159216f;   // 1/sqrt(512)

    // 0. weights -> bf16, bias concat
    prep_kernel<<<256, 256>>>(wq, wk, wv, wo, bq, bk, wb, b2);
    // 1. GroupNorm stats
    gn_stats_kernel<<<dim3(NG, BATCH), 256>>>(x, stats);
    // 2. fused apply + transpose -> hnt [HW, C] bf16
    gn_apply_transpose<<<dim3(HW / 32, CH / 32, BATCH), 256>>>(
        x, stats, gamma, beta, hnt);

    // 3. qk[p, 0:1024] = hnt . [Wq;Wk]^T + [bq;bk]   (M=4096, N=1024, K=512)
    bgemm<1,1><<<dim3(2 * CH / 128, HW / 128, BATCH), 256, SMEM>>>(
        hnt, wb, qk, b2, nullptr, CH, CH, CH, 2 * CH, sCH, 0, sQK, 1.f);
    // 4. v[c,p] = Wv . hnt^T + bv[c]                 (M=512, N=4096, K=512)
    bgemm<2,1><<<dim3(HW / 128, CH / 128, BATCH), 256, SMEM>>>(
        wvb, hnt, v, bv, nullptr, CH, CH, CH, HW, 0, sCH, sCH, 1.f);

    // 5. s[i,j] = (q . k^T) * scale                  (M=4096, N=4096, K=512)
    bgemm<0,0><<<dim3(HW / 128, HW / 128, BATCH), 256, SMEM>>>(
        qk, qk + CH, s, nullptr, nullptr, CH, 2 * CH, 2 * CH, HW, sQK, sQK, sHW, scale);

    // 6. softmax rows -> bf16 attn
    softmax_kernel<<<BATCH * HW, 256>>>(s, attn);

    // 7. ao_t[i,c] = attn . v^T                      (M=4096, N=512, K=4096)
    bgemm<0,1><<<dim3(CH / 128, HW / 128, BATCH), 256, SMEM>>>(
        attn, v, aot, nullptr, nullptr, HW, HW, HW, CH, sHW, sCH, sCH, 1.f);

    // 8. out[o,p] = Wo . ao_t^T + bo[o] + x          (M=512, N=4096, K=512)
    bgemm<3,0><<<dim3(HW / 128, CH / 128, BATCH), 256, SMEM>>>(
        wob, aot, out, bo, x, CH, CH, CH, HW, 0, sCH, sCH, 1.f);
}

// round 12
// speedup vs baseline: 1.1369x; 1.0131x over previous
#include <cuda_runtime.h>
#include <cuda_bf16.h>
#include <cstdint>

#define CH 512
#define HW 4096
#define BATCH 2
#define NG 32
#define CPG 16
#define EPSV 1e-6f

typedef __nv_bfloat16 bf16;

// Scratch (allocation-free rule: __device__ globals)
__device__ bf16   g_hnt[BATCH * CH * HW];                 // [HW, C]
__device__ bf16   g_qk [BATCH * HW * 2 * CH];             // [HW, 1024] q|k
__device__ bf16   g_v  [BATCH * CH * HW];                 // [C, HW]
__device__ bf16   g_aot[BATCH * CH * HW];                 // [HW, C]
__device__ float  g_s  [(size_t)BATCH * HW * HW];         // fp32 scores
__device__ bf16   g_attn[(size_t)BATCH * HW * HW];        // bf16 attn
__device__ bf16   g_wb [4 * CH * CH];                     // bf16 weights q,k,v,o
__device__ float  g_b2 [2 * CH];                          // bias concat bq|bk
__device__ float2 g_stats[BATCH * NG];                    // {mean, inv} per group

// ---------------------------------------------------------------------------
// helpers
// ---------------------------------------------------------------------------
__device__ __forceinline__ uint32_t smem_u32(const void* p) {
    uint32_t a;
    asm("{ .reg .u64 t; cvta.to.shared.u64 t, %1; cvt.u32.u64 %0, t; }"
        : "=r"(a) : "l"(p));
    return a;
}
__device__ __forceinline__ uint32_t pack_bf2(float a, float b) {
    __nv_bfloat162 h = __floats2bfloat162_rn(a, b);
    return *(uint32_t*)&h;
}
#define CP_ASYNC16(saddr, gaddr) \
    asm volatile("cp.async.cg.shared.global [%0], [%1], 16;" \
                 :: "r"(saddr), "l"(gaddr) : "memory")
#define CP_COMMIT() asm volatile("cp.async.commit_group;" ::: "memory")
#define CP_WAIT0()  asm volatile("cp.async.wait_group 0;"  ::: "memory")
#define CP_WAIT1()  asm volatile("cp.async.wait_group 1;"  ::: "memory")

#define LDSM4(r0, r1, r2, r3, addr) \
    asm volatile("ldmatrix.sync.aligned.m8n8.x4.shared.b16 {%0,%1,%2,%3}, [%4];" \
                 : "=r"(r0), "=r"(r1), "=r"(r2), "=r"(r3) : "r"(addr))

__device__ __forceinline__ void mma16(float (&d)[4], const uint32_t (&a)[4],
                                      const uint32_t (&b)[2]) {
    asm volatile(
        "mma.sync.aligned.m16n8k16.row.col.f32.bf16.bf16.f32 "
        "{%0,%1,%2,%3}, {%4,%5,%6,%7}, {%8,%9}, {%0,%1,%2,%3};"
        : "+f"(d[0]), "+f"(d[1]), "+f"(d[2]), "+f"(d[3])
        : "r"(a[0]), "r"(a[1]), "r"(a[2]), "r"(a[3]), "r"(b[0]), "r"(b[1]));
}

// load one k16-step fragment set for the warp: 4 A slabs + 4 B slabs (8 n8)
__device__ __forceinline__ void ldsm_set(uint32_t a0, uint32_t b0, uint32_t off,
                                         uint32_t (&af)[4][4], uint32_t (&bf)[8][2]) {
#pragma unroll
    for (int mt = 0; mt < 4; mt++)
        LDSM4(af[mt][0], af[mt][1], af[mt][2], af[mt][3], a0 + mt * 1280 + off);
#pragma unroll
    for (int h = 0; h < 4; h++)
        LDSM4(bf[2*h][0], bf[2*h][1], bf[2*h+1][0], bf[2*h+1][1],
              b0 + h * 1280 + off);
}
__device__ __forceinline__ void mma_all(float (&acc)[4][8][4],
                                        const uint32_t (&af)[4][4],
                                        const uint32_t (&bf)[8][2]) {
#pragma unroll
    for (int mt = 0; mt < 4; mt++)
#pragma unroll
        for (int nt = 0; nt < 8; nt++)
            mma16(acc[mt][nt], af[mt], bf[nt]);
}

// ---------------------------------------------------------------------------
// Pre-convert weights to bf16 (q,k,v,o) and concat bq|bk
// ---------------------------------------------------------------------------
__global__ __launch_bounds__(256) void prep_kernel(
    const float* __restrict__ w0, const float* __restrict__ w1,
    const float* __restrict__ w2, const float* __restrict__ w3,
    const float* __restrict__ bq, const float* __restrict__ bk,
    bf16* __restrict__ out, float* __restrict__ b2)
{
    const int n4 = CH * CH / 4;
    const int gid = blockIdx.x * 256 + threadIdx.x;
    const int stride = gridDim.x * 256;
    for (int i = gid; i < 4 * n4; i += stride) {
        const int m = i / n4, j = i - m * n4;
        const float* src = (m == 0) ? w0 : (m == 1) ? w1 : (m == 2) ? w2 : w3;
        float4 v = ((const float4*)src)[j];
        uint2 w;
        w.x = pack_bf2(v.x, v.y);
        w.y = pack_bf2(v.z, v.w);
        ((uint2*)out)[i] = w;
    }
    for (int i = gid; i < 2 * CH; i += stride)
        b2[i] = (i < CH) ? bq[i] : bk[i - CH];
}

// ---------------------------------------------------------------------------
// GroupNorm stats: one block per (group, batch) -> {mean, rsqrt(var+eps)}
// ---------------------------------------------------------------------------
__global__ __launch_bounds__(256) void gn_stats_kernel(
    const float* __restrict__ x, float2* __restrict__ stats)
{
    const int g = blockIdx.x;
    const int b = blockIdx.y;
    const size_t base = ((size_t)b * CH + g * CPG) * HW;
    const float* xg = x + base;

    float s = 0.f, ss = 0.f;
    for (int i = threadIdx.x; i < CPG * HW; i += 256) {
        float v = xg[i];
        s += v; ss += v * v;
    }
    for (int o = 16; o; o >>= 1) {
        s  += __shfl_xor_sync(0xffffffffu, s,  o);
        ss += __shfl_xor_sync(0xffffffffu, ss, o);
    }
    __shared__ float sw[8], sw2[8];
    const int warp = threadIdx.x >> 5, lane = threadIdx.x & 31;
    if (lane == 0) { sw[warp] = s; sw2[warp] = ss; }
    __syncthreads();
    if (warp == 0) {
        s  = (lane < 8) ? sw[lane]  : 0.f;
        ss = (lane < 8) ? sw2[lane] : 0.f;
        for (int o = 4; o; o >>= 1) {
            s  += __shfl_xor_sync(0xffffffffu, s,  o);
            ss += __shfl_xor_sync(0xffffffffu, ss, o);
        }
        if (lane == 0) {
            const float n    = (float)(CPG * HW);
            const float mean = s / n;
            const float var  = ss / n - mean * mean;
            stats[b * NG + g] = make_float2(mean, rsqrtf(var + EPSV));
        }
    }
}

// ---------------------------------------------------------------------------
// Fused GroupNorm-apply + transpose: x [C, HW] fp32 -> hnt [HW, C] bf16
// ---------------------------------------------------------------------------
__global__ __launch_bounds__(256) void gn_apply_transpose(
    const float* __restrict__ x, const float2* __restrict__ stats,
    const float* __restrict__ gamma, const float* __restrict__ beta,
    bf16* __restrict__ out)
{
    __shared__ float tile[32][33];
    const int b = blockIdx.z;
    x   += (size_t)b * CH * HW;
    out += (size_t)b * CH * HW;
    const int p0 = blockIdx.x * 32, c0 = blockIdx.y * 32;
    const int tx = threadIdx.x & 31, ty = threadIdx.x >> 5;
#pragma unroll
    for (int i = 0; i < 32; i += 8)
        tile[ty + i][tx] = x[(size_t)(c0 + ty + i) * HW + p0 + tx];
    __syncthreads();
    const int c = c0 + tx;
    const float2 st = stats[b * NG + (c >> 4)];
    const float sc = st.y * gamma[c];
    const float sh = beta[c] - st.x * sc;
#pragma unroll
    for (int i = 0; i < 32; i += 8)
        out[(size_t)(p0 + ty + i) * CH + c] =
            __float2bfloat16_rn(tile[tx][ty + i] * sc + sh);
}

// ---------------------------------------------------------------------------
// bf16 mma.sync GEMM: D = scale * A(M,K) . B(N,K)^T  (+epilogue)
// MODE: 0=scale only, 1=+bias[n], 2=+bias[m], 3=+bias[m]+res[m,n]
// OT:   0 -> fp32 output, 1 -> bf16 output
// 128x128 CTA tile, BK=32, 3-stage cp.async, 128 threads (4 warps),
// warp grid 2m x 2n, warp tile 64x64 (32 MMAs per k16 step).
// Software-pipelined frag double-buffer (convoy-free); 2 CTAs/SM decouple
// barriers so the tensor pipes never drain.
// ---------------------------------------------------------------------------
#define STG_B 10240
template<int MODE, int OT>
__global__ __launch_bounds__(128, 2) void bgemm(
    const bf16* __restrict__ A, const bf16* __restrict__ B,
    void* __restrict__ Cv,
    const float* __restrict__ bias, const float* __restrict__ res,
    int K, int lda, int ldb, int ldc,
    long long sA, long long sB, long long sC, float scale)
{
    extern __shared__ char sm[];
    const uint32_t Abase = smem_u32(sm);
    const uint32_t Bbase = Abase + 3 * STG_B;

    const int tid = threadIdx.x, lane = tid & 31, wid = tid >> 5;
    const int wm = wid & 1, wn = wid >> 1;          // warp grid 2m x 2n
    const int grp = lane >> 2, tig = lane & 3;
    const int bz = blockIdx.z;
    A += bz * sA; B += bz * sB;
    const float* resb = (MODE == 3) ? res + bz * sC : nullptr;
    const int m0 = blockIdx.y * 128, n0 = blockIdx.x * 128;

    // cp.async: lr = tid>>2 (0..31), chunk = (tid&3)*16B; rows lr,+32,+64,+96
    const int lr = tid >> 2;
    const int lc8 = (tid & 3) * 8;
    const bf16* Ag = A + (size_t)(m0 + lr) * lda + lc8;
    const bf16* Bg = B + (size_t)(n0 + lr) * ldb + lc8;
    const uint32_t sa0 = Abase + (uint32_t)(lr * 80 + (tid & 3) * 16);
    const uint32_t sb0 = Bbase + (uint32_t)(lr * 80 + (tid & 3) * 16);
    const uint32_t r32 = 32 * 80;

    // ldmatrix base lane addresses (stage 0, k-step 0)
    const uint32_t la_row = lane & 15, la_k = (lane >> 4) * 16;
    const uint32_t aaddr0 = Abase + (uint32_t)((wm * 64 + la_row) * 80) + la_k;
    const uint32_t lb_row = ((lane >> 4) * 8) + (lane & 7);
    const uint32_t lb_k = ((lane >> 3) & 1) * 16;
    const uint32_t baddr0 = Bbase + (uint32_t)((wn * 64 + lb_row) * 80) + lb_k;

    float acc[4][8][4];
#pragma unroll
    for (int mt = 0; mt < 4; mt++)
#pragma unroll
        for (int nt = 0; nt < 8; nt++)
#pragma unroll
            for (int j = 0; j < 4; j++) acc[mt][nt][j] = 0.f;

    const int T = K >> 5;           // BK=32

    // prologue: stages 0,1
#pragma unroll
    for (int p = 0; p < 2; p++) {
        const size_t ko = (size_t)p * 32;
        const uint32_t st = p * STG_B;
#pragma unroll
        for (int h = 0; h < 4; h++) {
            CP_ASYNC16(sa0 + st + h * r32, Ag + (size_t)h * 32 * lda + ko);
            CP_ASYNC16(sb0 + st + h * r32, Bg + (size_t)h * 32 * ldb + ko);
        }
        CP_COMMIT();
    }
    CP_WAIT1();                     // stage 0 arrived
    __syncthreads();

    uint32_t af[2][4][4], bfr[2][8][2];
    ldsm_set(aaddr0, baddr0, 0, af[0], bfr[0]);       // stage 0, k-step 0

    int cur = 0, nxt = 2;
    for (int kt = 0; kt < T; kt++) {
        const uint32_t so = cur * STG_B;
        ldsm_set(aaddr0, baddr0, so + 32, af[1], bfr[1]);   // k-step 1
        mma_all(acc, af[0], bfr[0]);

        if (kt + 2 < T) {
            const size_t ko = (size_t)(kt + 2) * 32;
            const uint32_t st = nxt * STG_B;
#pragma unroll
            for (int h = 0; h < 4; h++) {
                CP_ASYNC16(sa0 + st + h * r32, Ag + (size_t)h * 32 * lda + ko);
                CP_ASYNC16(sb0 + st + h * r32, Bg + (size_t)h * 32 * ldb + ko);
            }
        }
        CP_COMMIT();

        const int nstage = (cur + 1 == 3) ? 0 : cur + 1;
        if (kt + 1 < T) {
            CP_WAIT1();             // next stage data arrived
            __syncthreads();        // all warps done reading the reuse slot
            ldsm_set(aaddr0, baddr0, nstage * STG_B, af[0], bfr[0]);
        }
        mma_all(acc, af[1], bfr[1]);
        cur = nstage;
        nxt = (nxt + 1 == 3) ? 0 : nxt + 1;
    }

    // Epilogue
    float* Cf = (float*)Cv + ((OT == 0) ? bz * sC : 0);
    bf16*  Cb = (bf16*)Cv  + ((OT == 1) ? bz * sC : 0);
#pragma unroll
    for (int mt = 0; mt < 4; mt++) {
        const int r0 = m0 + wm * 64 + mt * 16 + grp;
        float bm0 = 0.f, bm1 = 0.f;
        if (MODE == 2 || MODE == 3) { bm0 = bias[r0]; bm1 = bias[r0 + 8]; }
#pragma unroll
        for (int nt = 0; nt < 8; nt++) {
            const int c = n0 + wn * 64 + nt * 8 + tig * 2;
            const float* d = acc[mt][nt];
            float2 o0 = { d[0] * scale, d[1] * scale };
            float2 o1 = { d[2] * scale, d[3] * scale };
            if (MODE == 1) {
                const float2 bn = *(const float2*)&bias[c];
                o0.x += bn.x; o0.y += bn.y; o1.x += bn.x; o1.y += bn.y;
            }
            if (MODE == 2 || MODE == 3) {
                o0.x += bm0; o0.y += bm0; o1.x += bm1; o1.y += bm1;
            }
            const size_t i0 = (size_t)r0 * ldc + c;
            const size_t i1 = (size_t)(r0 + 8) * ldc + c;
            if (MODE == 3) {
                const float2 r0v = *(const float2*)&resb[i0];
                const float2 r1v = *(const float2*)&resb[i1];
                o0.x += r0v.x; o0.y += r0v.y; o1.x += r1v.x; o1.y += r1v.y;
            }
            if (OT == 0) {
                *(float2*)&Cf[i0] = o0;
                *(float2*)&Cf[i1] = o1;
            } else {
                *(uint32_t*)&Cb[i0] = pack_bf2(o0.x, o0.y);
                *(uint32_t*)&Cb[i1] = pack_bf2(o1.x, o1.y);
            }
        }
    }
}

// ---------------------------------------------------------------------------
// Row softmax: fp32 scores in -> bf16 attn out
// ---------------------------------------------------------------------------
__global__ __launch_bounds__(256) void softmax_kernel(
    const float* __restrict__ s, bf16* __restrict__ attn)
{
    const float4* p = (const float4*)(s + (size_t)blockIdx.x * HW);
    uint2* po = (uint2*)(attn + (size_t)blockIdx.x * HW);
    const int t = threadIdx.x;
    const int warp = t >> 5, lane = t & 31;
    __shared__ float sh[8];

    float4 v[4];
    float mx = -3.4e38f;
#pragma unroll
    for (int i = 0; i < 4; i++) {
        v[i] = p[t + i * 256];
        mx = fmaxf(mx, fmaxf(fmaxf(v[i].x, v[i].y), fmaxf(v[i].z, v[i].w)));
    }
    for (int o = 16; o; o >>= 1) mx = fmaxf(mx, __shfl_xor_sync(0xffffffffu, mx, o));
    if (lane == 0) sh[warp] = mx;
    __syncthreads();
    if (warp == 0) {
        float m = (lane < 8) ? sh[lane] : -3.4e38f;
        for (int o = 4; o; o >>= 1) m = fmaxf(m, __shfl_xor_sync(0xffffffffu, m, o));
        if (lane == 0) sh[0] = m;
    }
    __syncthreads();
    mx = sh[0];
    __syncthreads();

    float sum = 0.f;
#pragma unroll
    for (int i = 0; i < 4; i++) {
        v[i].x = __expf(v[i].x - mx);
        v[i].y = __expf(v[i].y - mx);
        v[i].z = __expf(v[i].z - mx);
        v[i].w = __expf(v[i].w - mx);
        sum += v[i].x + v[i].y + v[i].z + v[i].w;
    }
    for (int o = 16; o; o >>= 1) sum += __shfl_xor_sync(0xffffffffu, sum, o);
    if (lane == 0) sh[warp] = sum;
    __syncthreads();
    if (warp == 0) {
        float m = (lane < 8) ? sh[lane] : 0.f;
        for (int o = 4; o; o >>= 1) m += __shfl_xor_sync(0xffffffffu, m, o);
        if (lane == 0) sh[0] = m;
    }
    __syncthreads();
    const float inv = 1.0f / sh[0];
#pragma unroll
    for (int i = 0; i < 4; i++) {
        uint2 w;
        w.x = pack_bf2(v[i].x * inv, v[i].y * inv);
        w.y = pack_bf2(v[i].z * inv, v[i].w * inv);
        po[t + i * 256] = w;
    }
}

// ---------------------------------------------------------------------------
extern "C" void kernel_launch(void* const* d_in, const int* in_sizes, int n_in,
                              void* d_out, int out_size)
{
    const float* x     = (const float*)d_in[0];
    const float* gamma = (const float*)d_in[1];
    const float* beta  = (const float*)d_in[2];
    const float* wq    = (const float*)d_in[3];
    const float* bq    = (const float*)d_in[4];
    const float* wk    = (const float*)d_in[5];
    const float* bk    = (const float*)d_in[6];
    const float* wv    = (const float*)d_in[7];
    const float* bv    = (const float*)d_in[8];
    const float* wo    = (const float*)d_in[9];
    const float* bo    = (const float*)d_in[10];
    float* out = (float*)d_out;

    float *s, *b2;
    float2* stats;
    bf16 *hnt, *qk, *v, *aot, *attn, *wb;
    cudaGetSymbolAddress((void**)&hnt,   g_hnt);
    cudaGetSymbolAddress((void**)&qk,    g_qk);
    cudaGetSymbolAddress((void**)&v,     g_v);
    cudaGetSymbolAddress((void**)&aot,   g_aot);
    cudaGetSymbolAddress((void**)&s,     g_s);
    cudaGetSymbolAddress((void**)&attn,  g_attn);
    cudaGetSymbolAddress((void**)&wb,    g_wb);
    cudaGetSymbolAddress((void**)&b2,    g_b2);
    cudaGetSymbolAddress((void**)&stats, g_stats);
    const bf16* wvb = wb + 2 * CH * CH;
    const bf16* wob = wb + 3 * CH * CH;

    const int SMEM = 6 * STG_B;       // 61440 B
    static int smem_set = 0;
    if (!smem_set) {
        cudaFuncSetAttribute(bgemm<1,1>, cudaFuncAttributeMaxDynamicSharedMemorySize, SMEM);
        cudaFuncSetAttribute(bgemm<2,1>, cudaFuncAttributeMaxDynamicSharedMemorySize, SMEM);
        cudaFuncSetAttribute(bgemm<0,0>, cudaFuncAttributeMaxDynamicSharedMemorySize, SMEM);
        cudaFuncSetAttribute(bgemm<0,1>, cudaFuncAttributeMaxDynamicSharedMemorySize, SMEM);
        cudaFuncSetAttribute(bgemm<3,0>, cudaFuncAttributeMaxDynamicSharedMemorySize, SMEM);
        smem_set = 1;
    }

    const long long sCH  = (long long)CH * HW;
    const long long sQK  = (long long)HW * 2 * CH;
    const long long sHW  = (long long)HW * HW;
    const float scale = 0.044194173824159216f;   // 1/sqrt(512)

    // 0. weights -> bf16, bias concat
    prep_kernel<<<256, 256>>>(wq, wk, wv, wo, bq, bk, wb, b2);
    // 1. GroupNorm stats
    gn_stats_kernel<<<dim3(NG, BATCH), 256>>>(x, stats);
    // 2. fused apply + transpose -> hnt [HW, C] bf16
    gn_apply_transpose<<<dim3(HW / 32, CH / 32, BATCH), 256>>>(
        x, stats, gamma, beta, hnt);

    // 3. qk[p, 0:1024] = hnt . [Wq;Wk]^T + [bq;bk]   (M=4096, N=1024, K=512)
    bgemm<1,1><<<dim3(2 * CH / 128, HW / 128, BATCH), 128, SMEM>>>(
        hnt, wb, qk, b2, nullptr, CH, CH, CH, 2 * CH, sCH, 0, sQK, 1.f);
    // 4. v[c,p] = Wv . hnt^T + bv[c]                 (M=512, N=4096, K=512)
    bgemm<2,1><<<dim3(HW / 128, CH / 128, BATCH), 128, SMEM>>>(
        wvb, hnt, v, bv, nullptr, CH, CH, CH, HW, 0, sCH, sCH, 1.f);

    // 5. s[i,j] = (q . k^T) * scale                  (M=4096, N=4096, K=512)
    bgemm<0,0><<<dim3(HW / 128, HW / 128, BATCH), 128, SMEM>>>(
        qk, qk + CH, s, nullptr, nullptr, CH, 2 * CH, 2 * CH, HW, sQK, sQK, sHW, scale);

    // 6. softmax rows -> bf16 attn
    softmax_kernel<<<BATCH * HW, 256>>>(s, attn);

    // 7. ao_t[i,c] = attn . v^T                      (M=4096, N=512, K=4096)
    bgemm<0,1><<<dim3(CH / 128, HW / 128, BATCH), 128, SMEM>>>(
        attn, v, aot, nullptr, nullptr, HW, HW, HW, CH, sHW, sCH, sCH, 1.f);

    // 8. out[o,p] = Wo . ao_t^T + bo[o] + x          (M=512, N=4096, K=512)
    bgemm<3,0><<<dim3(HW / 128, CH / 128, BATCH), 128, SMEM>>>(
        wob, aot, out, bo, x, CH, CH, CH, HW, 0, sCH, sCH, 1.f);
}

// round 13
// speedup vs baseline: 1.2928x; 1.1371x over previous
#include <cuda_runtime.h>
#include <cuda_bf16.h>
#include <cuda_fp16.h>
#include <cstdint>

#define CH 512
#define HW 4096
#define BATCH 2
#define NG 32
#define CPG 16
#define EPSV 1e-6f

typedef __nv_bfloat16 bf16;
typedef __half fp16;

// Scratch (allocation-free rule: __device__ globals)
__device__ bf16   g_hnt[BATCH * CH * HW];                 // [HW, C]
__device__ bf16   g_qk [BATCH * HW * 2 * CH];             // [HW, 1024] q|k
__device__ bf16   g_v  [BATCH * CH * HW];                 // [C, HW]
__device__ bf16   g_aot[BATCH * CH * HW];                 // [HW, C]
__device__ fp16   g_s  [(size_t)BATCH * HW * HW];         // fp16 scores (67MB)
__device__ bf16   g_attn[(size_t)BATCH * HW * HW];        // bf16 attn
__device__ bf16   g_wb [4 * CH * CH];                     // bf16 weights q,k,v,o
__device__ float  g_b2 [2 * CH];                          // bias concat bq|bk
__device__ float2 g_stats[BATCH * NG];                    // {mean, inv} per group

// ---------------------------------------------------------------------------
// helpers
// ---------------------------------------------------------------------------
__device__ __forceinline__ uint32_t smem_u32(const void* p) {
    uint32_t a;
    asm("{ .reg .u64 t; cvta.to.shared.u64 t, %1; cvt.u32.u64 %0, t; }"
        : "=r"(a) : "l"(p));
    return a;
}
__device__ __forceinline__ uint32_t pack_bf2(float a, float b) {
    __nv_bfloat162 h = __floats2bfloat162_rn(a, b);
    return *(uint32_t*)&h;
}
__device__ __forceinline__ uint32_t pack_hf2(float a, float b) {
    __half2 h = __floats2half2_rn(a, b);
    return *(uint32_t*)&h;
}
#define CP_ASYNC16(saddr, gaddr) \
    asm volatile("cp.async.cg.shared.global [%0], [%1], 16;" \
                 :: "r"(saddr), "l"(gaddr) : "memory")
#define CP_COMMIT() asm volatile("cp.async.commit_group;" ::: "memory")
#define CP_WAIT0()  asm volatile("cp.async.wait_group 0;"  ::: "memory")
#define CP_WAIT1()  asm volatile("cp.async.wait_group 1;"  ::: "memory")

#define LDSM4(r0, r1, r2, r3, addr) \
    asm volatile("ldmatrix.sync.aligned.m8n8.x4.shared.b16 {%0,%1,%2,%3}, [%4];" \
                 : "=r"(r0), "=r"(r1), "=r"(r2), "=r"(r3) : "r"(addr))

__device__ __forceinline__ void mma16(float (&d)[4], const uint32_t (&a)[4],
                                      const uint32_t (&b)[2]) {
    asm volatile(
        "mma.sync.aligned.m16n8k16.row.col.f32.bf16.bf16.f32 "
        "{%0,%1,%2,%3}, {%4,%5,%6,%7}, {%8,%9}, {%0,%1,%2,%3};"
        : "+f"(d[0]), "+f"(d[1]), "+f"(d[2]), "+f"(d[3])
        : "r"(a[0]), "r"(a[1]), "r"(a[2]), "r"(a[3]), "r"(b[0]), "r"(b[1]));
}

#define RS 144                       // smem row stride (64 bf16 + 16B pad)
#define SLAB (16 * RS)               // 16-row slab stride

// load one k16-step fragment set: 4 A slabs + 4 B slabs (8 n8 tiles)
__device__ __forceinline__ void ldsm_set(uint32_t a0, uint32_t b0, uint32_t off,
                                         uint32_t (&af)[4][4], uint32_t (&bf)[8][2]) {
#pragma unroll
    for (int mt = 0; mt < 4; mt++)
        LDSM4(af[mt][0], af[mt][1], af[mt][2], af[mt][3], a0 + mt * SLAB + off);
#pragma unroll
    for (int h = 0; h < 4; h++)
        LDSM4(bf[2*h][0], bf[2*h][1], bf[2*h+1][0], bf[2*h+1][1],
              b0 + h * SLAB + off);
}
__device__ __forceinline__ void mma_all(float (&acc)[4][8][4],
                                        const uint32_t (&af)[4][4],
                                        const uint32_t (&bf)[8][2]) {
#pragma unroll
    for (int mt = 0; mt < 4; mt++)
#pragma unroll
        for (int nt = 0; nt < 8; nt++)
            mma16(acc[mt][nt], af[mt], bf[nt]);
}

// ---------------------------------------------------------------------------
// Pre-convert weights to bf16 (q,k,v,o) and concat bq|bk
// ---------------------------------------------------------------------------
__global__ __launch_bounds__(256) void prep_kernel(
    const float* __restrict__ w0, const float* __restrict__ w1,
    const float* __restrict__ w2, const float* __restrict__ w3,
    const float* __restrict__ bq, const float* __restrict__ bk,
    bf16* __restrict__ out, float* __restrict__ b2)
{
    const int n4 = CH * CH / 4;
    const int gid = blockIdx.x * 256 + threadIdx.x;
    const int stride = gridDim.x * 256;
    for (int i = gid; i < 4 * n4; i += stride) {
        const int m = i / n4, j = i - m * n4;
        const float* src = (m == 0) ? w0 : (m == 1) ? w1 : (m == 2) ? w2 : w3;
        float4 v = ((const float4*)src)[j];
        uint2 w;
        w.x = pack_bf2(v.x, v.y);
        w.y = pack_bf2(v.z, v.w);
        ((uint2*)out)[i] = w;
    }
    for (int i = gid; i < 2 * CH; i += stride)
        b2[i] = (i < CH) ? bq[i] : bk[i - CH];
}

// ---------------------------------------------------------------------------
// GroupNorm stats: one block per (group, batch) -> {mean, rsqrt(var+eps)}
// ---------------------------------------------------------------------------
__global__ __launch_bounds__(256) void gn_stats_kernel(
    const float* __restrict__ x, float2* __restrict__ stats)
{
    const int g = blockIdx.x;
    const int b = blockIdx.y;
    const size_t base = ((size_t)b * CH + g * CPG) * HW;
    const float* xg = x + base;

    float s = 0.f, ss = 0.f;
    for (int i = threadIdx.x; i < CPG * HW; i += 256) {
        float v = xg[i];
        s += v; ss += v * v;
    }
    for (int o = 16; o; o >>= 1) {
        s  += __shfl_xor_sync(0xffffffffu, s,  o);
        ss += __shfl_xor_sync(0xffffffffu, ss, o);
    }
    __shared__ float sw[8], sw2[8];
    const int warp = threadIdx.x >> 5, lane = threadIdx.x & 31;
    if (lane == 0) { sw[warp] = s; sw2[warp] = ss; }
    __syncthreads();
    if (warp == 0) {
        s  = (lane < 8) ? sw[lane]  : 0.f;
        ss = (lane < 8) ? sw2[lane] : 0.f;
        for (int o = 4; o; o >>= 1) {
            s  += __shfl_xor_sync(0xffffffffu, s,  o);
            ss += __shfl_xor_sync(0xffffffffu, ss, o);
        }
        if (lane == 0) {
            const float n    = (float)(CPG * HW);
            const float mean = s / n;
            const float var  = ss / n - mean * mean;
            stats[b * NG + g] = make_float2(mean, rsqrtf(var + EPSV));
        }
    }
}

// ---------------------------------------------------------------------------
// Fused GroupNorm-apply + transpose: x [C, HW] fp32 -> hnt [HW, C] bf16
// ---------------------------------------------------------------------------
__global__ __launch_bounds__(256) void gn_apply_transpose(
    const float* __restrict__ x, const float2* __restrict__ stats,
    const float* __restrict__ gamma, const float* __restrict__ beta,
    bf16* __restrict__ out)
{
    __shared__ float tile[32][33];
    const int b = blockIdx.z;
    x   += (size_t)b * CH * HW;
    out += (size_t)b * CH * HW;
    const int p0 = blockIdx.x * 32, c0 = blockIdx.y * 32;
    const int tx = threadIdx.x & 31, ty = threadIdx.x >> 5;
#pragma unroll
    for (int i = 0; i < 32; i += 8)
        tile[ty + i][tx] = x[(size_t)(c0 + ty + i) * HW + p0 + tx];
    __syncthreads();
    const int c = c0 + tx;
    const float2 st = stats[b * NG + (c >> 4)];
    const float sc = st.y * gamma[c];
    const float sh = beta[c] - st.x * sc;
#pragma unroll
    for (int i = 0; i < 32; i += 8)
        out[(size_t)(p0 + ty + i) * CH + c] =
            __float2bfloat16_rn(tile[tx][ty + i] * sc + sh);
}

// ---------------------------------------------------------------------------
// bf16 mma.sync GEMM: D = scale * A(M,K) . B(N,K)^T  (+epilogue)
// MODE: 0=scale only, 1=+bias[n], 2=+bias[m], 3=+bias[m]+res[m,n]
// OT:   0 -> fp32 output, 1 -> bf16 output, 2 -> fp16 output
// 128x128 CTA tile, BK=64 (4 k16 steps, halved barrier count), 3-stage
// cp.async, 128 threads (4 warps, 2x2 grid, warp tile 64x64). Frag
// double-buffer keeps tensor work abutting barriers; 2 CTAs/SM decouple.
// ---------------------------------------------------------------------------
#define STG (128 * RS)               // 18432 B per operand-stage
template<int MODE, int OT>
__global__ __launch_bounds__(128, 2) void bgemm(
    const bf16* __restrict__ A, const bf16* __restrict__ B,
    void* __restrict__ Cv,
    const float* __restrict__ bias, const float* __restrict__ res,
    int K, int lda, int ldb, int ldc,
    long long sA, long long sB, long long sC, float scale)
{
    extern __shared__ char sm[];
    const uint32_t Abase = smem_u32(sm);
    const uint32_t Bbase = Abase + 3 * STG;

    const int tid = threadIdx.x, lane = tid & 31, wid = tid >> 5;
    const int wm = wid & 1, wn = wid >> 1;          // warp grid 2m x 2n
    const int grp = lane >> 2, tig = lane & 3;
    const int bz = blockIdx.z;
    A += bz * sA; B += bz * sB;
    const float* resb = (MODE == 3) ? res + bz * sC : nullptr;
    const int m0 = blockIdx.y * 128, n0 = blockIdx.x * 128;

    // cp.async: row = tid>>3 (+16 per pass, 8 passes), chunk = (tid&7)*16B
    const int lr = tid >> 3;
    const bf16* Ag = A + (size_t)(m0 + lr) * lda + (tid & 7) * 8;
    const bf16* Bg = B + (size_t)(n0 + lr) * ldb + (tid & 7) * 8;
    const uint32_t sa0 = Abase + (uint32_t)(lr * RS + (tid & 7) * 16);
    const uint32_t sb0 = Bbase + (uint32_t)(lr * RS + (tid & 7) * 16);
    const uint32_t r16 = 16 * RS;

    // ldmatrix base lane addresses (stage 0, k-step 0)
    const uint32_t la_row = lane & 15, la_k = (lane >> 4) * 16;
    const uint32_t aaddr0 = Abase + (uint32_t)((wm * 64 + la_row) * RS) + la_k;
    const uint32_t lb_row = ((lane >> 4) * 8) + (lane & 7);
    const uint32_t lb_k = ((lane >> 3) & 1) * 16;
    const uint32_t baddr0 = Bbase + (uint32_t)((wn * 64 + lb_row) * RS) + lb_k;

    float acc[4][8][4];
#pragma unroll
    for (int mt = 0; mt < 4; mt++)
#pragma unroll
        for (int nt = 0; nt < 8; nt++)
#pragma unroll
            for (int j = 0; j < 4; j++) acc[mt][nt][j] = 0.f;

    const int T = K >> 6;           // BK=64

    // prologue: stages 0,1
#pragma unroll
    for (int p = 0; p < 2; p++) {
        const size_t ko = (size_t)p * 64;
        const uint32_t st = p * STG;
#pragma unroll
        for (int h = 0; h < 8; h++) {
            CP_ASYNC16(sa0 + st + h * r16, Ag + (size_t)h * 16 * lda + ko);
            CP_ASYNC16(sb0 + st + h * r16, Bg + (size_t)h * 16 * ldb + ko);
        }
        CP_COMMIT();
    }
    CP_WAIT1();                     // stage 0 arrived
    __syncthreads();

    uint32_t af[2][4][4], bfr[2][8][2];
    ldsm_set(aaddr0, baddr0, 0, af[0], bfr[0]);       // stage 0, k-step 0

    int cur = 0, nxt = 2;
    for (int kt = 0; kt < T; kt++) {
        const uint32_t so = cur * STG;
        ldsm_set(aaddr0, baddr0, so + 32, af[1], bfr[1]);
        mma_all(acc, af[0], bfr[0]);
        ldsm_set(aaddr0, baddr0, so + 64, af[0], bfr[0]);
        mma_all(acc, af[1], bfr[1]);
        ldsm_set(aaddr0, baddr0, so + 96, af[1], bfr[1]);
        mma_all(acc, af[0], bfr[0]);

        if (kt + 2 < T) {
            const size_t ko = (size_t)(kt + 2) * 64;
            const uint32_t st = nxt * STG;
#pragma unroll
            for (int h = 0; h < 8; h++) {
                CP_ASYNC16(sa0 + st + h * r16, Ag + (size_t)h * 16 * lda + ko);
                CP_ASYNC16(sb0 + st + h * r16, Bg + (size_t)h * 16 * ldb + ko);
            }
        }
        CP_COMMIT();

        const int nstage = (cur + 1 == 3) ? 0 : cur + 1;
        if (kt + 1 < T) {
            CP_WAIT1();             // next stage data arrived
            __syncthreads();        // all warps done reading the reuse slot
            ldsm_set(aaddr0, baddr0, nstage * STG, af[0], bfr[0]);
        }
        mma_all(acc, af[1], bfr[1]);
        cur = nstage;
        nxt = (nxt + 1 == 3) ? 0 : nxt + 1;
    }

    // Epilogue
    float* Cf = (float*)Cv + ((OT == 0) ? bz * sC : 0);
    bf16*  Cb = (bf16*)Cv  + ((OT == 1) ? bz * sC : 0);
    fp16*  Ch = (fp16*)Cv  + ((OT == 2) ? bz * sC : 0);
#pragma unroll
    for (int mt = 0; mt < 4; mt++) {
        const int r0 = m0 + wm * 64 + mt * 16 + grp;
        float bm0 = 0.f, bm1 = 0.f;
        if (MODE == 2 || MODE == 3) { bm0 = bias[r0]; bm1 = bias[r0 + 8]; }
#pragma unroll
        for (int nt = 0; nt < 8; nt++) {
            const int c = n0 + wn * 64 + nt * 8 + tig * 2;
            const float* d = acc[mt][nt];
            float2 o0 = { d[0] * scale, d[1] * scale };
            float2 o1 = { d[2] * scale, d[3] * scale };
            if (MODE == 1) {
                const float2 bn = *(const float2*)&bias[c];
                o0.x += bn.x; o0.y += bn.y; o1.x += bn.x; o1.y += bn.y;
            }
            if (MODE == 2 || MODE == 3) {
                o0.x += bm0; o0.y += bm0; o1.x += bm1; o1.y += bm1;
            }
            const size_t i0 = (size_t)r0 * ldc + c;
            const size_t i1 = (size_t)(r0 + 8) * ldc + c;
            if (MODE == 3) {
                const float2 r0v = *(const float2*)&resb[i0];
                const float2 r1v = *(const float2*)&resb[i1];
                o0.x += r0v.x; o0.y += r0v.y; o1.x += r1v.x; o1.y += r1v.y;
            }
            if (OT == 0) {
                *(float2*)&Cf[i0] = o0;
                *(float2*)&Cf[i1] = o1;
            } else if (OT == 1) {
                *(uint32_t*)&Cb[i0] = pack_bf2(o0.x, o0.y);
                *(uint32_t*)&Cb[i1] = pack_bf2(o1.x, o1.y);
            } else {
                *(uint32_t*)&Ch[i0] = pack_hf2(o0.x, o0.y);
                *(uint32_t*)&Ch[i1] = pack_hf2(o1.x, o1.y);
            }
        }
    }
}

// ---------------------------------------------------------------------------
// Row softmax: fp16 scores in -> bf16 attn out
// ---------------------------------------------------------------------------
__global__ __launch_bounds__(256) void softmax_kernel(
    const fp16* __restrict__ s, bf16* __restrict__ attn)
{
    const uint2* p = (const uint2*)(s + (size_t)blockIdx.x * HW);   // 4 halves
    uint2* po = (uint2*)(attn + (size_t)blockIdx.x * HW);           // 4 bf16
    const int t = threadIdx.x;
    const int warp = t >> 5, lane = t & 31;
    __shared__ float sh[8];

    float v[16];
    float mx = -3.4e38f;
#pragma unroll
    for (int i = 0; i < 4; i++) {
        const uint2 r = p[t + i * 256];
        const float2 f0 = __half22float2(*(const __half2*)&r.x);
        const float2 f1 = __half22float2(*(const __half2*)&r.y);
        v[i*4+0] = f0.x; v[i*4+1] = f0.y; v[i*4+2] = f1.x; v[i*4+3] = f1.y;
        mx = fmaxf(mx, fmaxf(fmaxf(f0.x, f0.y), fmaxf(f1.x, f1.y)));
    }
    for (int o = 16; o; o >>= 1) mx = fmaxf(mx, __shfl_xor_sync(0xffffffffu, mx, o));
    if (lane == 0) sh[warp] = mx;
    __syncthreads();
    if (warp == 0) {
        float m = (lane < 8) ? sh[lane] : -3.4e38f;
        for (int o = 4; o; o >>= 1) m = fmaxf(m, __shfl_xor_sync(0xffffffffu, m, o));
        if (lane == 0) sh[0] = m;
    }
    __syncthreads();
    mx = sh[0];
    __syncthreads();

    float sum = 0.f;
#pragma unroll
    for (int i = 0; i < 16; i++) {
        v[i] = __expf(v[i] - mx);
        sum += v[i];
    }
    for (int o = 16; o; o >>= 1) sum += __shfl_xor_sync(0xffffffffu, sum, o);
    if (lane == 0) sh[warp] = sum;
    __syncthreads();
    if (warp == 0) {
        float m = (lane < 8) ? sh[lane] : 0.f;
        for (int o = 4; o; o >>= 1) m += __shfl_xor_sync(0xffffffffu, m, o);
        if (lane == 0) sh[0] = m;
    }
    __syncthreads();
    const float inv = 1.0f / sh[0];
#pragma unroll
    for (int i = 0; i < 4; i++) {
        uint2 w;
        w.x = pack_bf2(v[i*4+0] * inv, v[i*4+1] * inv);
        w.y = pack_bf2(v[i*4+2] * inv, v[i*4+3] * inv);
        po[t + i * 256] = w;
    }
}

// ---------------------------------------------------------------------------
extern "C" void kernel_launch(void* const* d_in, const int* in_sizes, int n_in,
                              void* d_out, int out_size)
{
    const float* x     = (const float*)d_in[0];
    const float* gamma = (const float*)d_in[1];
    const float* beta  = (const float*)d_in[2];
    const float* wq    = (const float*)d_in[3];
    const float* bq    = (const float*)d_in[4];
    const float* wk    = (const float*)d_in[5];
    const float* bk    = (const float*)d_in[6];
    const float* wv    = (const float*)d_in[7];
    const float* bv    = (const float*)d_in[8];
    const float* wo    = (const float*)d_in[9];
    const float* bo    = (const float*)d_in[10];
    float* out = (float*)d_out;

    float *b2;
    fp16* s;
    float2* stats;
    bf16 *hnt, *qk, *v, *aot, *attn, *wb;
    cudaGetSymbolAddress((void**)&hnt,   g_hnt);
    cudaGetSymbolAddress((void**)&qk,    g_qk);
    cudaGetSymbolAddress((void**)&v,     g_v);
    cudaGetSymbolAddress((void**)&aot,   g_aot);
    cudaGetSymbolAddress((void**)&s,     g_s);
    cudaGetSymbolAddress((void**)&attn,  g_attn);
    cudaGetSymbolAddress((void**)&wb,    g_wb);
    cudaGetSymbolAddress((void**)&b2,    g_b2);
    cudaGetSymbolAddress((void**)&stats, g_stats);
    const bf16* wvb = wb + 2 * CH * CH;
    const bf16* wob = wb + 3 * CH * CH;

    const int SMEM = 6 * STG;       // 110592 B
    static int smem_set = 0;
    if (!smem_set) {
        cudaFuncSetAttribute(bgemm<1,1>, cudaFuncAttributeMaxDynamicSharedMemorySize, SMEM);
        cudaFuncSetAttribute(bgemm<2,1>, cudaFuncAttributeMaxDynamicSharedMemorySize, SMEM);
        cudaFuncSetAttribute(bgemm<0,2>, cudaFuncAttributeMaxDynamicSharedMemorySize, SMEM);
        cudaFuncSetAttribute(bgemm<0,1>, cudaFuncAttributeMaxDynamicSharedMemorySize, SMEM);
        cudaFuncSetAttribute(bgemm<3,0>, cudaFuncAttributeMaxDynamicSharedMemorySize, SMEM);
        smem_set = 1;
    }

    const long long sCH  = (long long)CH * HW;
    const long long sQK  = (long long)HW * 2 * CH;
    const long long sHW  = (long long)HW * HW;
    const float scale = 0.044194173824159216f;   // 1/sqrt(512)

    // 0. weights -> bf16, bias concat
    prep_kernel<<<256, 256>>>(wq, wk, wv, wo, bq, bk, wb, b2);
    // 1. GroupNorm stats
    gn_stats_kernel<<<dim3(NG, BATCH), 256>>>(x, stats);
    // 2. fused apply + transpose -> hnt [HW, C] bf16
    gn_apply_transpose<<<dim3(HW / 32, CH / 32, BATCH), 256>>>(
        x, stats, gamma, beta, hnt);

    // 3. qk[p, 0:1024] = hnt . [Wq;Wk]^T + [bq;bk]   (M=4096, N=1024, K=512)
    bgemm<1,1><<<dim3(2 * CH / 128, HW / 128, BATCH), 128, SMEM>>>(
        hnt, wb, qk, b2, nullptr, CH, CH, CH, 2 * CH, sCH, 0, sQK, 1.f);
    // 4. v[c,p] = Wv . hnt^T + bv[c]                 (M=512, N=4096, K=512)
    bgemm<2,1><<<dim3(HW / 128, CH / 128, BATCH), 128, SMEM>>>(
        wvb, hnt, v, bv, nullptr, CH, CH, CH, HW, 0, sCH, sCH, 1.f);

    // 5. s[i,j] = (q . k^T) * scale -> fp16          (M=4096, N=4096, K=512)
    bgemm<0,2><<<dim3(HW / 128, HW / 128, BATCH), 128, SMEM>>>(
        qk, qk + CH, s, nullptr, nullptr, CH, 2 * CH, 2 * CH, HW, sQK, sQK, sHW, scale);

    // 6. softmax rows (fp16 in) -> bf16 attn
    softmax_kernel<<<BATCH * HW, 256>>>(s, attn);

    // 7. ao_t[i,c] = attn . v^T                      (M=4096, N=512, K=4096)
    bgemm<0,1><<<dim3(CH / 128, HW / 128, BATCH), 128, SMEM>>>(
        attn, v, aot, nullptr, nullptr, HW, HW, HW, CH, sHW, sCH, sCH, 1.f);

    // 8. out[o,p] = Wo . ao_t^T + bo[o] + x          (M=512, N=4096, K=512)
    bgemm<3,0><<<dim3(HW / 128, CH / 128, BATCH), 128, SMEM>>>(
        wob, aot, out, bo, x, CH, CH, CH, HW, 0, sCH, sCH, 1.f);
}

// round 14
// speedup vs baseline: 1.3377x; 1.0348x over previous
#include <cuda_runtime.h>
#include <cuda_bf16.h>
#include <cuda_fp16.h>
#include <cstdint>

#define CH 512
#define HW 4096
#define BATCH 2
#define NG 32
#define CPG 16
#define EPSV 1e-6f

typedef __nv_bfloat16 bf16;
typedef __half fp16;

// Scratch (allocation-free rule: __device__ globals)
__device__ bf16   g_hnt[BATCH * CH * HW];                 // [HW, C]
__device__ bf16   g_qk [BATCH * HW * 2 * CH];             // [HW, 1024] q|k
__device__ bf16   g_v  [BATCH * CH * HW];                 // [C, HW]
__device__ bf16   g_aot[BATCH * CH * HW];                 // [HW, C]
__device__ fp16   g_s  [(size_t)BATCH * HW * HW];         // fp16 scores (67MB)
__device__ bf16   g_attn[(size_t)BATCH * HW * HW];        // bf16 attn
__device__ bf16   g_wb [4 * CH * CH];                     // bf16 weights q,k,v,o
__device__ float  g_b2 [2 * CH];                          // bias concat bq|bk
__device__ float2 g_stats[BATCH * NG];                    // {mean, inv} per group

// ---------------------------------------------------------------------------
// helpers
// ---------------------------------------------------------------------------
__device__ __forceinline__ uint32_t smem_u32(const void* p) {
    uint32_t a;
    asm("{ .reg .u64 t; cvta.to.shared.u64 t, %1; cvt.u32.u64 %0, t; }"
        : "=r"(a) : "l"(p));
    return a;
}
__device__ __forceinline__ uint32_t pack_bf2(float a, float b) {
    __nv_bfloat162 h = __floats2bfloat162_rn(a, b);
    return *(uint32_t*)&h;
}
__device__ __forceinline__ uint32_t pack_hf2(float a, float b) {
    __half2 h = __floats2half2_rn(a, b);
    return *(uint32_t*)&h;
}
#define CP_ASYNC16(saddr, gaddr) \
    asm volatile("cp.async.cg.shared.global [%0], [%1], 16;" \
                 :: "r"(saddr), "l"(gaddr) : "memory")
#define CP_COMMIT() asm volatile("cp.async.commit_group;" ::: "memory")
#define CP_WAIT4()  asm volatile("cp.async.wait_group 4;"  ::: "memory")

#define LDSM4(r0, r1, r2, r3, addr) \
    asm volatile("ldmatrix.sync.aligned.m8n8.x4.shared.b16 {%0,%1,%2,%3}, [%4];" \
                 : "=r"(r0), "=r"(r1), "=r"(r2), "=r"(r3) : "r"(addr))

__device__ __forceinline__ void mma16(float (&d)[4], const uint32_t (&a)[4],
                                      const uint32_t (&b)[2]) {
    asm volatile(
        "mma.sync.aligned.m16n8k16.row.col.f32.bf16.bf16.f32 "
        "{%0,%1,%2,%3}, {%4,%5,%6,%7}, {%8,%9}, {%0,%1,%2,%3};"
        : "+f"(d[0]), "+f"(d[1]), "+f"(d[2]), "+f"(d[3])
        : "r"(a[0]), "r"(a[1]), "r"(a[2]), "r"(a[3]), "r"(b[0]), "r"(b[1]));
}

// ---- 6-stage swizzled smem: 64B rows, chunk' = chunk ^ ((row>>1)&3) ------
#define NST 6
#define SOP 8192                 // 128 rows * 64 B, per operand per stage

// load one k16-step fragment set: 4 A slabs + 4 B slabs (8 n8 tiles)
__device__ __forceinline__ void ldsm_set(
    const uint32_t (&aaddr)[4], const uint32_t (&baddr)[4],
    uint32_t ak, uint32_t bk, uint32_t stg,
    uint32_t (&af)[4][4], uint32_t (&bf)[8][2])
{
#pragma unroll
    for (int mt = 0; mt < 4; mt++)
        LDSM4(af[mt][0], af[mt][1], af[mt][2], af[mt][3], aaddr[mt] + stg + ak);
#pragma unroll
    for (int h = 0; h < 4; h++)
        LDSM4(bf[2*h][0], bf[2*h][1], bf[2*h+1][0], bf[2*h+1][1],
              baddr[h] + stg + bk);
}
__device__ __forceinline__ void mma_all(float (&acc)[4][8][4],
                                        const uint32_t (&af)[4][4],
                                        const uint32_t (&bf)[8][2]) {
#pragma unroll
    for (int mt = 0; mt < 4; mt++)
#pragma unroll
        for (int nt = 0; nt < 8; nt++)
            mma16(acc[mt][nt], af[mt], bf[nt]);
}

// ---------------------------------------------------------------------------
// Pre-convert weights to bf16 (q,k,v,o) and concat bq|bk
// ---------------------------------------------------------------------------
__global__ __launch_bounds__(256) void prep_kernel(
    const float* __restrict__ w0, const float* __restrict__ w1,
    const float* __restrict__ w2, const float* __restrict__ w3,
    const float* __restrict__ bq, const float* __restrict__ bk,
    bf16* __restrict__ out, float* __restrict__ b2)
{
    const int n4 = CH * CH / 4;
    const int gid = blockIdx.x * 256 + threadIdx.x;
    const int stride = gridDim.x * 256;
    for (int i = gid; i < 4 * n4; i += stride) {
        const int m = i / n4, j = i - m * n4;
        const float* src = (m == 0) ? w0 : (m == 1) ? w1 : (m == 2) ? w2 : w3;
        float4 v = ((const float4*)src)[j];
        uint2 w;
        w.x = pack_bf2(v.x, v.y);
        w.y = pack_bf2(v.z, v.w);
        ((uint2*)out)[i] = w;
    }
    for (int i = gid; i < 2 * CH; i += stride)
        b2[i] = (i < CH) ? bq[i] : bk[i - CH];
}

// ---------------------------------------------------------------------------
// GroupNorm stats: one block per (group, batch) -> {mean, rsqrt(var+eps)}
// ---------------------------------------------------------------------------
__global__ __launch_bounds__(256) void gn_stats_kernel(
    const float* __restrict__ x, float2* __restrict__ stats)
{
    const int g = blockIdx.x;
    const int b = blockIdx.y;
    const size_t base = ((size_t)b * CH + g * CPG) * HW;
    const float* xg = x + base;

    float s = 0.f, ss = 0.f;
    for (int i = threadIdx.x; i < CPG * HW; i += 256) {
        float v = xg[i];
        s += v; ss += v * v;
    }
    for (int o = 16; o; o >>= 1) {
        s  += __shfl_xor_sync(0xffffffffu, s,  o);
        ss += __shfl_xor_sync(0xffffffffu, ss, o);
    }
    __shared__ float sw[8], sw2[8];
    const int warp = threadIdx.x >> 5, lane = threadIdx.x & 31;
    if (lane == 0) { sw[warp] = s; sw2[warp] = ss; }
    __syncthreads();
    if (warp == 0) {
        s  = (lane < 8) ? sw[lane]  : 0.f;
        ss = (lane < 8) ? sw2[lane] : 0.f;
        for (int o = 4; o; o >>= 1) {
            s  += __shfl_xor_sync(0xffffffffu, s,  o);
            ss += __shfl_xor_sync(0xffffffffu, ss, o);
        }
        if (lane == 0) {
            const float n    = (float)(CPG * HW);
            const float mean = s / n;
            const float var  = ss / n - mean * mean;
            stats[b * NG + g] = make_float2(mean, rsqrtf(var + EPSV));
        }
    }
}

// ---------------------------------------------------------------------------
// Fused GroupNorm-apply + transpose: x [C, HW] fp32 -> hnt [HW, C] bf16
// ---------------------------------------------------------------------------
__global__ __launch_bounds__(256) void gn_apply_transpose(
    const float* __restrict__ x, const float2* __restrict__ stats,
    const float* __restrict__ gamma, const float* __restrict__ beta,
    bf16* __restrict__ out)
{
    __shared__ float tile[32][33];
    const int b = blockIdx.z;
    x   += (size_t)b * CH * HW;
    out += (size_t)b * CH * HW;
    const int p0 = blockIdx.x * 32, c0 = blockIdx.y * 32;
    const int tx = threadIdx.x & 31, ty = threadIdx.x >> 5;
#pragma unroll
    for (int i = 0; i < 32; i += 8)
        tile[ty + i][tx] = x[(size_t)(c0 + ty + i) * HW + p0 + tx];
    __syncthreads();
    const int c = c0 + tx;
    const float2 st = stats[b * NG + (c >> 4)];
    const float sc = st.y * gamma[c];
    const float sh = beta[c] - st.x * sc;
#pragma unroll
    for (int i = 0; i < 32; i += 8)
        out[(size_t)(p0 + ty + i) * CH + c] =
            __float2bfloat16_rn(tile[tx][ty + i] * sc + sh);
}

// ---------------------------------------------------------------------------
// bf16 mma.sync GEMM: D = scale * A(M,K) . B(N,K)^T  (+epilogue)
// MODE: 0=scale only, 1=+bias[n], 2=+bias[m], 3=+bias[m]+res[m,n]
// OT:   0 -> fp32 output, 1 -> bf16 output, 2 -> fp16 output
// 128x128 CTA tile, BK=32, **6-stage** cp.async ring with wait_group 4
// (prefetch distance 4-5 tiles to cover L2/DRAM latency), 128 threads
// (4 warps 2x2, warp tile 64x64), XOR-swizzled 64B-row smem (conflict-free,
// no padding -> 96KB/CTA, 2 CTAs/SM). Frag double-buffer from R11.
// ---------------------------------------------------------------------------
template<int MODE, int OT>
__global__ __launch_bounds__(128, 2) void bgemm(
    const bf16* __restrict__ A, const bf16* __restrict__ B,
    void* __restrict__ Cv,
    const float* __restrict__ bias, const float* __restrict__ res,
    int K, int lda, int ldb, int ldc,
    long long sA, long long sB, long long sC, float scale)
{
    extern __shared__ char sm[];
    const uint32_t Abase = smem_u32(sm);
    const uint32_t Bbase = Abase + NST * SOP;

    const int tid = threadIdx.x, lane = tid & 31, wid = tid >> 5;
    const int wm = wid & 1, wn = wid >> 1;          // warp grid 2m x 2n
    const int grp = lane >> 2, tig = lane & 3;
    const int bz = blockIdx.z;
    A += bz * sA; B += bz * sB;
    const float* resb = (MODE == 3) ? res + bz * sC : nullptr;
    const int m0 = blockIdx.y * 128, n0 = blockIdx.x * 128;

    // cp.async: row lr = tid>>2 (+32 per h, 4 passes), logical chunk c = tid&3
    const int lr = tid >> 2;
    const int c  = tid & 3;
    const int cx = c ^ ((lr >> 1) & 3);             // swizzled chunk
    const bf16* Ag = A + (size_t)(m0 + lr) * lda + c * 8;
    const bf16* Bg = B + (size_t)(n0 + lr) * ldb + c * 8;
    const uint32_t sa0 = Abase + (uint32_t)(lr * 64 + cx * 16);
    const uint32_t sb0 = Bbase + (uint32_t)(lr * 64 + cx * 16);
    const uint32_t r32 = 32 * 64;                   // +32 rows (bytes)

    // ldmatrix lane addresses (row part only; k-chunk applied per step)
    const uint32_t la_row = lane & 15;
    uint32_t aaddr[4];
#pragma unroll
    for (int mt = 0; mt < 4; mt++)
        aaddr[mt] = Abase + (uint32_t)((wm * 64 + mt * 16 + la_row) * 64);
    const uint32_t acb = lane >> 4;                 // 0/1 : k-halves
    const uint32_t axa = (la_row >> 1) & 3;
    const uint32_t akoff[2] = { ((acb    ) ^ axa) * 16, ((acb + 2) ^ axa) * 16 };

    const uint32_t lb_row = ((lane >> 4) * 8) + (lane & 7);
    uint32_t baddr[4];
#pragma unroll
    for (int h = 0; h < 4; h++)
        baddr[h] = Bbase + (uint32_t)((wn * 64 + h * 16 + lb_row) * 64);
    const uint32_t bcb = (lane >> 3) & 1;
    const uint32_t bxa = (lb_row >> 1) & 3;
    const uint32_t bkoff[2] = { ((bcb    ) ^ bxa) * 16, ((bcb + 2) ^ bxa) * 16 };

    float acc[4][8][4];
#pragma unroll
    for (int mt = 0; mt < 4; mt++)
#pragma unroll
        for (int nt = 0; nt < 8; nt++)
#pragma unroll
            for (int j = 0; j < 4; j++) acc[mt][nt][j] = 0.f;

    const int T = K >> 5;           // BK=32

    // prologue: stages 0..4 (5 groups in flight)
#pragma unroll
    for (int p = 0; p < 5; p++) {
        const size_t ko = (size_t)p * 32;
        const uint32_t st = p * SOP;
#pragma unroll
        for (int h = 0; h < 4; h++) {
            CP_ASYNC16(sa0 + st + h * r32, Ag + (size_t)h * 32 * lda + ko);
            CP_ASYNC16(sb0 + st + h * r32, Bg + (size_t)h * 32 * ldb + ko);
        }
        CP_COMMIT();
    }
    CP_WAIT4();                     // stage 0 landed
    __syncthreads();

    uint32_t af[2][4][4], bfr[2][8][2];
    ldsm_set(aaddr, baddr, akoff[0], bkoff[0], 0, af[0], bfr[0]);

    int cur = 0;
    for (int kt = 0; kt < T; kt++) {
        const uint32_t so = cur * SOP;
        ldsm_set(aaddr, baddr, akoff[1], bkoff[1], so, af[1], bfr[1]);
        mma_all(acc, af[0], bfr[0]);

        if (kt + 5 < T) {           // refill slot (kt+5)%NST; its last read was
            const size_t ko = (size_t)(kt + 5) * 32;   // iter kt-1 (barrier'd)
            const int slot = (kt + 5) % NST;
            const uint32_t st = slot * SOP;
#pragma unroll
            for (int h = 0; h < 4; h++) {
                CP_ASYNC16(sa0 + st + h * r32, Ag + (size_t)h * 32 * lda + ko);
                CP_ASYNC16(sb0 + st + h * r32, Bg + (size_t)h * 32 * ldb + ko);
            }
        }
        CP_COMMIT();                // commit every iter (possibly empty group)

        const int nstage = (cur + 1 == NST) ? 0 : cur + 1;
        if (kt + 1 < T) {
            CP_WAIT4();             // next stage data arrived (4 iters of slack)
            __syncthreads();        // cross-thread visibility + reuse guard
            ldsm_set(aaddr, baddr, akoff[0], bkoff[0], nstage * SOP,
                     af[0], bfr[0]);
        }
        mma_all(acc, af[1], bfr[1]);
        cur = nstage;
    }

    // Epilogue
    float* Cf = (float*)Cv + ((OT == 0) ? bz * sC : 0);
    bf16*  Cb = (bf16*)Cv  + ((OT == 1) ? bz * sC : 0);
    fp16*  Ch = (fp16*)Cv  + ((OT == 2) ? bz * sC : 0);
#pragma unroll
    for (int mt = 0; mt < 4; mt++) {
        const int r0 = m0 + wm * 64 + mt * 16 + grp;
        float bm0 = 0.f, bm1 = 0.f;
        if (MODE == 2 || MODE == 3) { bm0 = bias[r0]; bm1 = bias[r0 + 8]; }
#pragma unroll
        for (int nt = 0; nt < 8; nt++) {
            const int cc = n0 + wn * 64 + nt * 8 + tig * 2;
            const float* d = acc[mt][nt];
            float2 o0 = { d[0] * scale, d[1] * scale };
            float2 o1 = { d[2] * scale, d[3] * scale };
            if (MODE == 1) {
                const float2 bn = *(const float2*)&bias[cc];
                o0.x += bn.x; o0.y += bn.y; o1.x += bn.x; o1.y += bn.y;
            }
            if (MODE == 2 || MODE == 3) {
                o0.x += bm0; o0.y += bm0; o1.x += bm1; o1.y += bm1;
            }
            const size_t i0 = (size_t)r0 * ldc + cc;
            const size_t i1 = (size_t)(r0 + 8) * ldc + cc;
            if (MODE == 3) {
                const float2 r0v = *(const float2*)&resb[i0];
                const float2 r1v = *(const float2*)&resb[i1];
                o0.x += r0v.x; o0.y += r0v.y; o1.x += r1v.x; o1.y += r1v.y;
            }
            if (OT == 0) {
                *(float2*)&Cf[i0] = o0;
                *(float2*)&Cf[i1] = o1;
            } else if (OT == 1) {
                *(uint32_t*)&Cb[i0] = pack_bf2(o0.x, o0.y);
                *(uint32_t*)&Cb[i1] = pack_bf2(o1.x, o1.y);
            } else {
                *(uint32_t*)&Ch[i0] = pack_hf2(o0.x, o0.y);
                *(uint32_t*)&Ch[i1] = pack_hf2(o1.x, o1.y);
            }
        }
    }
}

// ---------------------------------------------------------------------------
// Row softmax: fp16 scores in -> bf16 attn out
// ---------------------------------------------------------------------------
__global__ __launch_bounds__(256) void softmax_kernel(
    const fp16* __restrict__ s, bf16* __restrict__ attn)
{
    const uint2* p = (const uint2*)(s + (size_t)blockIdx.x * HW);   // 4 halves
    uint2* po = (uint2*)(attn + (size_t)blockIdx.x * HW);           // 4 bf16
    const int t = threadIdx.x;
    const int warp = t >> 5, lane = t & 31;
    __shared__ float sh[8];

    float v[16];
    float mx = -3.4e38f;
#pragma unroll
    for (int i = 0; i < 4; i++) {
        const uint2 r = p[t + i * 256];
        const float2 f0 = __half22float2(*(const __half2*)&r.x);
        const float2 f1 = __half22float2(*(const __half2*)&r.y);
        v[i*4+0] = f0.x; v[i*4+1] = f0.y; v[i*4+2] = f1.x; v[i*4+3] = f1.y;
        mx = fmaxf(mx, fmaxf(fmaxf(f0.x, f0.y), fmaxf(f1.x, f1.y)));
    }
    for (int o = 16; o; o >>= 1) mx = fmaxf(mx, __shfl_xor_sync(0xffffffffu, mx, o));
    if (lane == 0) sh[warp] = mx;
    __syncthreads();
    if (warp == 0) {
        float m = (lane < 8) ? sh[lane] : -3.4e38f;
        for (int o = 4; o; o >>= 1) m = fmaxf(m, __shfl_xor_sync(0xffffffffu, m, o));
        if (lane == 0) sh[0] = m;
    }
    __syncthreads();
    mx = sh[0];
    __syncthreads();

    float sum = 0.f;
#pragma unroll
    for (int i = 0; i < 16; i++) {
        v[i] = __expf(v[i] - mx);
        sum += v[i];
    }
    for (int o = 16; o; o >>= 1) sum += __shfl_xor_sync(0xffffffffu, sum, o);
    if (lane == 0) sh[warp] = sum;
    __syncthreads();
    if (warp == 0) {
        float m = (lane < 8) ? sh[lane] : 0.f;
        for (int o = 4; o; o >>= 1) m += __shfl_xor_sync(0xffffffffu, m, o);
        if (lane == 0) sh[0] = m;
    }
    __syncthreads();
    const float inv = 1.0f / sh[0];
#pragma unroll
    for (int i = 0; i < 4; i++) {
        uint2 w;
        w.x = pack_bf2(v[i*4+0] * inv, v[i*4+1] * inv);
        w.y = pack_bf2(v[i*4+2] * inv, v[i*4+3] * inv);
        po[t + i * 256] = w;
    }
}

// ---------------------------------------------------------------------------
extern "C" void kernel_launch(void* const* d_in, const int* in_sizes, int n_in,
                              void* d_out, int out_size)
{
    const float* x     = (const float*)d_in[0];
    const float* gamma = (const float*)d_in[1];
    const float* beta  = (const float*)d_in[2];
    const float* wq    = (const float*)d_in[3];
    const float* bq    = (const float*)d_in[4];
    const float* wk    = (const float*)d_in[5];
    const float* bk    = (const float*)d_in[6];
    const float* wv    = (const float*)d_in[7];
    const float* bv    = (const float*)d_in[8];
    const float* wo    = (const float*)d_in[9];
    const float* bo    = (const float*)d_in[10];
    float* out = (float*)d_out;

    float *b2;
    fp16* s;
    float2* stats;
    bf16 *hnt, *qk, *v, *aot, *attn, *wb;
    cudaGetSymbolAddress((void**)&hnt,   g_hnt);
    cudaGetSymbolAddress((void**)&qk,    g_qk);
    cudaGetSymbolAddress((void**)&v,     g_v);
    cudaGetSymbolAddress((void**)&aot,   g_aot);
    cudaGetSymbolAddress((void**)&s,     g_s);
    cudaGetSymbolAddress((void**)&attn,  g_attn);
    cudaGetSymbolAddress((void**)&wb,    g_wb);
    cudaGetSymbolAddress((void**)&b2,    g_b2);
    cudaGetSymbolAddress((void**)&stats, g_stats);
    const bf16* wvb = wb + 2 * CH * CH;
    const bf16* wob = wb + 3 * CH * CH;

    const int SMEM = 2 * NST * SOP;   // 98304 B
    static int smem_set = 0;
    if (!smem_set) {
        cudaFuncSetAttribute(bgemm<1,1>, cudaFuncAttributeMaxDynamicSharedMemorySize, SMEM);
        cudaFuncSetAttribute(bgemm<2,1>, cudaFuncAttributeMaxDynamicSharedMemorySize, SMEM);
        cudaFuncSetAttribute(bgemm<0,2>, cudaFuncAttributeMaxDynamicSharedMemorySize, SMEM);
        cudaFuncSetAttribute(bgemm<0,1>, cudaFuncAttributeMaxDynamicSharedMemorySize, SMEM);
        cudaFuncSetAttribute(bgemm<3,0>, cudaFuncAttributeMaxDynamicSharedMemorySize, SMEM);
        smem_set = 1;
    }

    const long long sCH  = (long long)CH * HW;
    const long long sQK  = (long long)HW * 2 * CH;
    const long long sHW  = (long long)HW * HW;
    const float scale = 0.044194173824159216f;   // 1/sqrt(512)

    // 0. weights -> bf16, bias concat
    prep_kernel<<<256, 256>>>(wq, wk, wv, wo, bq, bk, wb, b2);
    // 1. GroupNorm stats
    gn_stats_kernel<<<dim3(NG, BATCH), 256>>>(x, stats);
    // 2. fused apply + transpose -> hnt [HW, C] bf16
    gn_apply_transpose<<<dim3(HW / 32, CH / 32, BATCH), 256>>>(
        x, stats, gamma, beta, hnt);

    // 3. qk[p, 0:1024] = hnt . [Wq;Wk]^T + [bq;bk]   (M=4096, N=1024, K=512)
    bgemm<1,1><<<dim3(2 * CH / 128, HW / 128, BATCH), 128, SMEM>>>(
        hnt, wb, qk, b2, nullptr, CH, CH, CH, 2 * CH, sCH, 0, sQK, 1.f);
    // 4. v[c,p] = Wv . hnt^T + bv[c]                 (M=512, N=4096, K=512)
    bgemm<2,1><<<dim3(HW / 128, CH / 128, BATCH), 128, SMEM>>>(
        wvb, hnt, v, bv, nullptr, CH, CH, CH, HW, 0, sCH, sCH, 1.f);

    // 5. s[i,j] = (q . k^T) * scale -> fp16          (M=4096, N=4096, K=512)
    bgemm<0,2><<<dim3(HW / 128, HW / 128, BATCH), 128, SMEM>>>(
        qk, qk + CH, s, nullptr, nullptr, CH, 2 * CH, 2 * CH, HW, sQK, sQK, sHW, scale);

    // 6. softmax rows (fp16 in) -> bf16 attn
    softmax_kernel<<<BATCH * HW, 256>>>(s, attn);

    // 7. ao_t[i,c] = attn . v^T                      (M=4096, N=512, K=4096)
    bgemm<0,1><<<dim3(CH / 128, HW / 128, BATCH), 128, SMEM>>>(
        attn, v, aot, nullptr, nullptr, HW, HW, HW, CH, sHW, sCH, sCH, 1.f);

    // 8. out[o,p] = Wo . ao_t^T + bo[o] + x          (M=512, N=4096, K=512)
    bgemm<3,0><<<dim3(HW / 128, CH / 128, BATCH), 128, SMEM>>>(
        wob, aot, out, bo, x, CH, CH, CH, HW, 0, sCH, sCH, 1.f);
}

// round 15
// speedup vs baseline: 1.3607x; 1.0171x over previous
#include <cuda_runtime.h>
#include <cuda_fp16.h>
#include <cstdint>

#define CH 512
#define HW 4096
#define BATCH 2
#define NG 32
#define CPG 16
#define EPSV 1e-6f

typedef __half fp16;

// Scratch (allocation-free rule: __device__ globals)
__device__ fp16   g_hnt[BATCH * CH * HW];                 // [HW, C]
__device__ fp16   g_qk [BATCH * HW * 2 * CH];             // [HW, 1024] q|k
__device__ fp16   g_v  [BATCH * CH * HW];                 // [C, HW]
__device__ fp16   g_aot[BATCH * CH * HW];                 // [HW, C]
__device__ fp16   g_es [(size_t)BATCH * HW * HW];         // fp16 exp-scores
__device__ fp16   g_wb [4 * CH * CH];                     // fp16 weights q,k,v,o
__device__ float  g_b2 [2 * CH];                          // bias concat bq|bk
__device__ float2 g_stats[BATCH * NG];                    // {mean, inv} per group
__device__ float  g_rinv[BATCH * HW];                     // 1/rowsum

// ---------------------------------------------------------------------------
// helpers
// ---------------------------------------------------------------------------
__device__ __forceinline__ uint32_t smem_u32(const void* p) {
    uint32_t a;
    asm("{ .reg .u64 t; cvta.to.shared.u64 t, %1; cvt.u32.u64 %0, t; }"
        : "=r"(a) : "l"(p));
    return a;
}
__device__ __forceinline__ uint32_t pack_hf2(float a, float b) {
    __half2 h = __floats2half2_rn(a, b);
    return *(uint32_t*)&h;
}
#define CP_ASYNC16(saddr, gaddr) \
    asm volatile("cp.async.cg.shared.global [%0], [%1], 16;" \
                 :: "r"(saddr), "l"(gaddr) : "memory")
#define CP_COMMIT() asm volatile("cp.async.commit_group;" ::: "memory")
#define CP_WAIT4()  asm volatile("cp.async.wait_group 4;"  ::: "memory")

#define LDSM4(r0, r1, r2, r3, addr) \
    asm volatile("ldmatrix.sync.aligned.m8n8.x4.shared.b16 {%0,%1,%2,%3}, [%4];" \
                 : "=r"(r0), "=r"(r1), "=r"(r2), "=r"(r3) : "r"(addr))

__device__ __forceinline__ void mma16(float (&d)[4], const uint32_t (&a)[4],
                                      const uint32_t (&b)[2]) {
    asm volatile(
        "mma.sync.aligned.m16n8k16.row.col.f32.f16.f16.f32 "
        "{%0,%1,%2,%3}, {%4,%5,%6,%7}, {%8,%9}, {%0,%1,%2,%3};"
        : "+f"(d[0]), "+f"(d[1]), "+f"(d[2]), "+f"(d[3])
        : "r"(a[0]), "r"(a[1]), "r"(a[2]), "r"(a[3]), "r"(b[0]), "r"(b[1]));
}

// ---- 6-stage swizzled smem: 64B rows, chunk' = chunk ^ ((row>>1)&3) ------
#define NST 6
#define SOP 8192                 // 128 rows * 64 B, per operand per stage

__device__ __forceinline__ void ldsm_set(
    const uint32_t (&aaddr)[4], const uint32_t (&baddr)[4],
    uint32_t ak, uint32_t bk, uint32_t stg,
    uint32_t (&af)[4][4], uint32_t (&bf)[8][2])
{
#pragma unroll
    for (int mt = 0; mt < 4; mt++)
        LDSM4(af[mt][0], af[mt][1], af[mt][2], af[mt][3], aaddr[mt] + stg + ak);
#pragma unroll
    for (int h = 0; h < 4; h++)
        LDSM4(bf[2*h][0], bf[2*h][1], bf[2*h+1][0], bf[2*h+1][1],
              baddr[h] + stg + bk);
}
__device__ __forceinline__ void mma_all(float (&acc)[4][8][4],
                                        const uint32_t (&af)[4][4],
                                        const uint32_t (&bf)[8][2]) {
#pragma unroll
    for (int mt = 0; mt < 4; mt++)
#pragma unroll
        for (int nt = 0; nt < 8; nt++)
            mma16(acc[mt][nt], af[mt], bf[nt]);
}

// ---------------------------------------------------------------------------
// Pre-convert weights to fp16 (q,k,v,o) and concat bq|bk
// ---------------------------------------------------------------------------
__global__ __launch_bounds__(256) void prep_kernel(
    const float* __restrict__ w0, const float* __restrict__ w1,
    const float* __restrict__ w2, const float* __restrict__ w3,
    const float* __restrict__ bq, const float* __restrict__ bk,
    fp16* __restrict__ out, float* __restrict__ b2)
{
    const int n4 = CH * CH / 4;
    const int gid = blockIdx.x * 256 + threadIdx.x;
    const int stride = gridDim.x * 256;
    for (int i = gid; i < 4 * n4; i += stride) {
        const int m = i / n4, j = i - m * n4;
        const float* src = (m == 0) ? w0 : (m == 1) ? w1 : (m == 2) ? w2 : w3;
        float4 v = ((const float4*)src)[j];
        uint2 w;
        w.x = pack_hf2(v.x, v.y);
        w.y = pack_hf2(v.z, v.w);
        ((uint2*)out)[i] = w;
    }
    for (int i = gid; i < 2 * CH; i += stride)
        b2[i] = (i < CH) ? bq[i] : bk[i - CH];
}

// ---------------------------------------------------------------------------
// GroupNorm stats: one block per (group, batch) -> {mean, rsqrt(var+eps)}
// ---------------------------------------------------------------------------
__global__ __launch_bounds__(256) void gn_stats_kernel(
    const float* __restrict__ x, float2* __restrict__ stats)
{
    const int g = blockIdx.x;
    const int b = blockIdx.y;
    const size_t base = ((size_t)b * CH + g * CPG) * HW;
    const float* xg = x + base;

    float s = 0.f, ss = 0.f;
    for (int i = threadIdx.x; i < CPG * HW; i += 256) {
        float v = xg[i];
        s += v; ss += v * v;
    }
    for (int o = 16; o; o >>= 1) {
        s  += __shfl_xor_sync(0xffffffffu, s,  o);
        ss += __shfl_xor_sync(0xffffffffu, ss, o);
    }
    __shared__ float sw[8], sw2[8];
    const int warp = threadIdx.x >> 5, lane = threadIdx.x & 31;
    if (lane == 0) { sw[warp] = s; sw2[warp] = ss; }
    __syncthreads();
    if (warp == 0) {
        s  = (lane < 8) ? sw[lane]  : 0.f;
        ss = (lane < 8) ? sw2[lane] : 0.f;
        for (int o = 4; o; o >>= 1) {
            s  += __shfl_xor_sync(0xffffffffu, s,  o);
            ss += __shfl_xor_sync(0xffffffffu, ss, o);
        }
        if (lane == 0) {
            const float n    = (float)(CPG * HW);
            const float mean = s / n;
            const float var  = ss / n - mean * mean;
            stats[b * NG + g] = make_float2(mean, rsqrtf(var + EPSV));
        }
    }
}

// ---------------------------------------------------------------------------
// Fused GroupNorm-apply + transpose: x [C, HW] fp32 -> hnt [HW, C] fp16
// ---------------------------------------------------------------------------
__global__ __launch_bounds__(256) void gn_apply_transpose(
    const float* __restrict__ x, const float2* __restrict__ stats,
    const float* __restrict__ gamma, const float* __restrict__ beta,
    fp16* __restrict__ out)
{
    __shared__ float tile[32][33];
    const int b = blockIdx.z;
    x   += (size_t)b * CH * HW;
    out += (size_t)b * CH * HW;
    const int p0 = blockIdx.x * 32, c0 = blockIdx.y * 32;
    const int tx = threadIdx.x & 31, ty = threadIdx.x >> 5;
#pragma unroll
    for (int i = 0; i < 32; i += 8)
        tile[ty + i][tx] = x[(size_t)(c0 + ty + i) * HW + p0 + tx];
    __syncthreads();
    const int c = c0 + tx;
    const float2 st = stats[b * NG + (c >> 4)];
    const float sc = st.y * gamma[c];
    const float sh = beta[c] - st.x * sc;
#pragma unroll
    for (int i = 0; i < 32; i += 8)
        out[(size_t)(p0 + ty + i) * CH + c] =
            __float2half_rn(tile[tx][ty + i] * sc + sh);
}

// ---------------------------------------------------------------------------
// fp16 mma.sync GEMM: D = f(scale * A(M,K) . B(N,K)^T)  (+epilogue)
// MODE: 0=scale only, 1=+bias[n], 2=+bias[m], 3=+bias[m]+res[m,n] (fp32 out),
//       4=exp2(acc*scale) (fused softmax numerator), 5=acc*rowscale[m]
// OT:   0 -> fp32 output, 1 -> fp16 output
// 128x128 CTA tile, BK=32, 6-stage cp.async ring (wait_group 4), 128 threads
// (4 warps 2x2, warp tile 64x64), XOR-swizzled 64B-row smem, frag dbl-buffer.
// ---------------------------------------------------------------------------
template<int MODE, int OT>
__global__ __launch_bounds__(128, 2) void bgemm(
    const fp16* __restrict__ A, const fp16* __restrict__ B,
    void* __restrict__ Cv,
    const float* __restrict__ bias, const float* __restrict__ res,
    int K, int lda, int ldb, int ldc,
    long long sA, long long sB, long long sC, float scale)
{
    extern __shared__ char sm[];
    const uint32_t Abase = smem_u32(sm);
    const uint32_t Bbase = Abase + NST * SOP;

    const int tid = threadIdx.x, lane = tid & 31, wid = tid >> 5;
    const int wm = wid & 1, wn = wid >> 1;          // warp grid 2m x 2n
    const int grp = lane >> 2, tig = lane & 3;
    const int bz = blockIdx.z;
    A += bz * sA; B += bz * sB;
    const float* resb = (MODE == 3) ? res + bz * sC : nullptr;
    const float* biasb = (MODE == 5) ? bias + bz * HW : bias;
    const int m0 = blockIdx.y * 128, n0 = blockIdx.x * 128;

    const int lr = tid >> 2;
    const int c  = tid & 3;
    const int cx = c ^ ((lr >> 1) & 3);             // swizzled chunk
    const fp16* Ag = A + (size_t)(m0 + lr) * lda + c * 8;
    const fp16* Bg = B + (size_t)(n0 + lr) * ldb + c * 8;
    const uint32_t sa0 = Abase + (uint32_t)(lr * 64 + cx * 16);
    const uint32_t sb0 = Bbase + (uint32_t)(lr * 64 + cx * 16);
    const uint32_t r32 = 32 * 64;

    const uint32_t la_row = lane & 15;
    uint32_t aaddr[4];
#pragma unroll
    for (int mt = 0; mt < 4; mt++)
        aaddr[mt] = Abase + (uint32_t)((wm * 64 + mt * 16 + la_row) * 64);
    const uint32_t acb = lane >> 4;
    const uint32_t axa = (la_row >> 1) & 3;
    const uint32_t akoff[2] = { ((acb    ) ^ axa) * 16, ((acb + 2) ^ axa) * 16 };

    const uint32_t lb_row = ((lane >> 4) * 8) + (lane & 7);
    uint32_t baddr[4];
#pragma unroll
    for (int h = 0; h < 4; h++)
        baddr[h] = Bbase + (uint32_t)((wn * 64 + h * 16 + lb_row) * 64);
    const uint32_t bcb = (lane >> 3) & 1;
    const uint32_t bxa = (lb_row >> 1) & 3;
    const uint32_t bkoff[2] = { ((bcb    ) ^ bxa) * 16, ((bcb + 2) ^ bxa) * 16 };

    float acc[4][8][4];
#pragma unroll
    for (int mt = 0; mt < 4; mt++)
#pragma unroll
        for (int nt = 0; nt < 8; nt++)
#pragma unroll
            for (int j = 0; j < 4; j++) acc[mt][nt][j] = 0.f;

    const int T = K >> 5;

    // prologue: stages 0..4
#pragma unroll
    for (int p = 0; p < 5; p++) {
        const size_t ko = (size_t)p * 32;
        const uint32_t st = p * SOP;
#pragma unroll
        for (int h = 0; h < 4; h++) {
            CP_ASYNC16(sa0 + st + h * r32, Ag + (size_t)h * 32 * lda + ko);
            CP_ASYNC16(sb0 + st + h * r32, Bg + (size_t)h * 32 * ldb + ko);
        }
        CP_COMMIT();
    }
    CP_WAIT4();
    __syncthreads();

    uint32_t af[2][4][4], bfr[2][8][2];
    ldsm_set(aaddr, baddr, akoff[0], bkoff[0], 0, af[0], bfr[0]);

    int cur = 0;
    for (int kt = 0; kt < T; kt++) {
        const uint32_t so = cur * SOP;
        ldsm_set(aaddr, baddr, akoff[1], bkoff[1], so, af[1], bfr[1]);
        mma_all(acc, af[0], bfr[0]);

        if (kt + 5 < T) {
            const size_t ko = (size_t)(kt + 5) * 32;
            const int slot = (kt + 5) % NST;
            const uint32_t st = slot * SOP;
#pragma unroll
            for (int h = 0; h < 4; h++) {
                CP_ASYNC16(sa0 + st + h * r32, Ag + (size_t)h * 32 * lda + ko);
                CP_ASYNC16(sb0 + st + h * r32, Bg + (size_t)h * 32 * ldb + ko);
            }
        }
        CP_COMMIT();

        const int nstage = (cur + 1 == NST) ? 0 : cur + 1;
        if (kt + 1 < T) {
            CP_WAIT4();
            __syncthreads();
            ldsm_set(aaddr, baddr, akoff[0], bkoff[0], nstage * SOP,
                     af[0], bfr[0]);
        }
        mma_all(acc, af[1], bfr[1]);
        cur = nstage;
    }

    // Epilogue
    float* Cf = (float*)Cv + ((OT == 0) ? bz * sC : 0);
    fp16*  Ch = (fp16*)Cv  + ((OT == 1) ? bz * sC : 0);
#pragma unroll
    for (int mt = 0; mt < 4; mt++) {
        const int r0 = m0 + wm * 64 + mt * 16 + grp;
        float bm0 = 0.f, bm1 = 0.f;
        if (MODE == 2 || MODE == 3 || MODE == 5) {
            bm0 = biasb[r0]; bm1 = biasb[r0 + 8];
        }
#pragma unroll
        for (int nt = 0; nt < 8; nt++) {
            const int cc = n0 + wn * 64 + nt * 8 + tig * 2;
            const float* d = acc[mt][nt];
            float2 o0, o1;
            if (MODE == 4) {
                o0.x = exp2f(d[0] * scale); o0.y = exp2f(d[1] * scale);
                o1.x = exp2f(d[2] * scale); o1.y = exp2f(d[3] * scale);
            } else if (MODE == 5) {
                o0.x = d[0] * bm0; o0.y = d[1] * bm0;
                o1.x = d[2] * bm1; o1.y = d[3] * bm1;
            } else {
                o0.x = d[0] * scale; o0.y = d[1] * scale;
                o1.x = d[2] * scale; o1.y = d[3] * scale;
                if (MODE == 1) {
                    const float2 bn = *(const float2*)&biasb[cc];
                    o0.x += bn.x; o0.y += bn.y; o1.x += bn.x; o1.y += bn.y;
                }
                if (MODE == 2 || MODE == 3) {
                    o0.x += bm0; o0.y += bm0; o1.x += bm1; o1.y += bm1;
                }
            }
            const size_t i0 = (size_t)r0 * ldc + cc;
            const size_t i1 = (size_t)(r0 + 8) * ldc + cc;
            if (MODE == 3) {
                const float2 r0v = *(const float2*)&resb[i0];
                const float2 r1v = *(const float2*)&resb[i1];
                o0.x += r0v.x; o0.y += r0v.y; o1.x += r1v.x; o1.y += r1v.y;
            }
            if (OT == 0) {
                *(float2*)&Cf[i0] = o0;
                *(float2*)&Cf[i1] = o1;
            } else {
                *(uint32_t*)&Ch[i0] = pack_hf2(o0.x, o0.y);
                *(uint32_t*)&Ch[i1] = pack_hf2(o1.x, o1.y);
            }
        }
    }
}

// ---------------------------------------------------------------------------
// Row sum of exp-scores -> 1/sum.  One 128-thread block per row.
// ---------------------------------------------------------------------------
__global__ __launch_bounds__(128) void rowsum_kernel(
    const fp16* __restrict__ es, float* __restrict__ rinv)
{
    const uint4* p = (const uint4*)(es + (size_t)blockIdx.x * HW);  // 8 halves
    const int t = threadIdx.x;
    const int warp = t >> 5, lane = t & 31;
    __shared__ float sh[4];

    float sum = 0.f;
#pragma unroll
    for (int i = 0; i < 4; i++) {
        const uint4 r = p[t + i * 128];
        const float2 f0 = __half22float2(*(const __half2*)&r.x);
        const float2 f1 = __half22float2(*(const __half2*)&r.y);
        const float2 f2 = __half22float2(*(const __half2*)&r.z);
        const float2 f3 = __half22float2(*(const __half2*)&r.w);
        sum += (f0.x + f0.y) + (f1.x + f1.y) + (f2.x + f2.y) + (f3.x + f3.y);
    }
    for (int o = 16; o; o >>= 1) sum += __shfl_xor_sync(0xffffffffu, sum, o);
    if (lane == 0) sh[warp] = sum;
    __syncthreads();
    if (t == 0) {
        const float s = sh[0] + sh[1] + sh[2] + sh[3];
        rinv[blockIdx.x] = 1.0f / s;
    }
}

// ---------------------------------------------------------------------------
extern "C" void kernel_launch(void* const* d_in, const int* in_sizes, int n_in,
                              void* d_out, int out_size)
{
    const float* x     = (const float*)d_in[0];
    const float* gamma = (const float*)d_in[1];
    const float* beta  = (const float*)d_in[2];
    const float* wq    = (const float*)d_in[3];
    const float* bq    = (const float*)d_in[4];
    const float* wk    = (const float*)d_in[5];
    const float* bk    = (const float*)d_in[6];
    const float* wv    = (const float*)d_in[7];
    const float* bv    = (const float*)d_in[8];
    const float* wo    = (const float*)d_in[9];
    const float* bo    = (const float*)d_in[10];
    float* out = (float*)d_out;

    float *b2, *rinv;
    float2* stats;
    fp16 *hnt, *qk, *v, *aot, *es, *wb;
    cudaGetSymbolAddress((void**)&hnt,   g_hnt);
    cudaGetSymbolAddress((void**)&qk,    g_qk);
    cudaGetSymbolAddress((void**)&v,     g_v);
    cudaGetSymbolAddress((void**)&aot,   g_aot);
    cudaGetSymbolAddress((void**)&es,    g_es);
    cudaGetSymbolAddress((void**)&wb,    g_wb);
    cudaGetSymbolAddress((void**)&b2,    g_b2);
    cudaGetSymbolAddress((void**)&stats, g_stats);
    cudaGetSymbolAddress((void**)&rinv,  g_rinv);
    const fp16* wvb = wb + 2 * CH * CH;
    const fp16* wob = wb + 3 * CH * CH;

    const int SMEM = 2 * NST * SOP;   // 98304 B
    static int smem_set = 0;
    if (!smem_set) {
        cudaFuncSetAttribute(bgemm<1,1>, cudaFuncAttributeMaxDynamicSharedMemorySize, SMEM);
        cudaFuncSetAttribute(bgemm<2,1>, cudaFuncAttributeMaxDynamicSharedMemorySize, SMEM);
        cudaFuncSetAttribute(bgemm<4,1>, cudaFuncAttributeMaxDynamicSharedMemorySize, SMEM);
        cudaFuncSetAttribute(bgemm<5,1>, cudaFuncAttributeMaxDynamicSharedMemorySize, SMEM);
        cudaFuncSetAttribute(bgemm<3,0>, cudaFuncAttributeMaxDynamicSharedMemorySize, SMEM);
        smem_set = 1;
    }

    const long long sCH  = (long long)CH * HW;
    const long long sQK  = (long long)HW * 2 * CH;
    const long long sHW  = (long long)HW * HW;
    // exp2 scale: (1/sqrt(512)) * log2(e)
    const float escale = 0.044194173824159216f * 1.4426950408889634f;

    // 0. weights -> fp16, bias concat
    prep_kernel<<<256, 256>>>(wq, wk, wv, wo, bq, bk, wb, b2);
    // 1. GroupNorm stats
    gn_stats_kernel<<<dim3(NG, BATCH), 256>>>(x, stats);
    // 2. fused apply + transpose -> hnt [HW, C] fp16
    gn_apply_transpose<<<dim3(HW / 32, CH / 32, BATCH), 256>>>(
        x, stats, gamma, beta, hnt);

    // 3. qk[p, 0:1024] = hnt . [Wq;Wk]^T + [bq;bk]   (M=4096, N=1024, K=512)
    bgemm<1,1><<<dim3(2 * CH / 128, HW / 128, BATCH), 128, SMEM>>>(
        hnt, wb, qk, b2, nullptr, CH, CH, CH, 2 * CH, sCH, 0, sQK, 1.f);
    // 4. v[c,p] = Wv . hnt^T + bv[c]                 (M=512, N=4096, K=512)
    bgemm<2,1><<<dim3(HW / 128, CH / 128, BATCH), 128, SMEM>>>(
        wvb, hnt, v, bv, nullptr, CH, CH, CH, HW, 0, sCH, sCH, 1.f);

    // 5. es[i,j] = exp(q.k^T * scale)  (fused softmax numerator, fp16)
    bgemm<4,1><<<dim3(HW / 128, HW / 128, BATCH), 128, SMEM>>>(
        qk, qk + CH, es, nullptr, nullptr, CH, 2 * CH, 2 * CH, HW, sQK, sQK, sHW, escale);

    // 6. rinv[i] = 1 / sum_j es[i,j]
    rowsum_kernel<<<BATCH * HW, 128>>>(es, rinv);

    // 7. ao_t[i,c] = (es . v^T)[i,c] * rinv[i]       (M=4096, N=512, K=4096)
    bgemm<5,1><<<dim3(CH / 128, HW / 128, BATCH), 128, SMEM>>>(
        es, v, aot, rinv, nullptr, HW, HW, HW, CH, sHW, sCH, sCH, 1.f);

    // 8. out[o,p] = Wo . ao_t^T + bo[o] + x          (M=512, N=4096, K=512)
    bgemm<3,0><<<dim3(HW / 128, CH / 128, BATCH), 128, SMEM>>>(
        wob, aot, out, bo, x, CH, CH, CH, HW, 0, sCH, sCH, 1.f);
}

// round 16
// speedup vs baseline: 1.4027x; 1.0309x over previous
#include <cuda_runtime.h>
#include <cuda_fp16.h>
#include <cstdint>

#define CH 512
#define HW 4096
#define BATCH 2
#define NG 32
#define CPG 16
#define EPSV 1e-6f

typedef __half fp16;

// Scratch (allocation-free rule: __device__ globals)
__device__ fp16   g_hnt[BATCH * CH * HW];                 // [HW, C]
__device__ fp16   g_qk [BATCH * HW * 2 * CH];             // [HW, 1024] q|k
__device__ fp16   g_v  [BATCH * CH * HW];                 // [C, HW]
__device__ fp16   g_aot[BATCH * CH * HW];                 // [HW, C]
__device__ fp16   g_es [(size_t)BATCH * HW * HW];         // fp16 exp-scores
__device__ fp16   g_wb [4 * CH * CH];                     // fp16 weights q,k,v,o
__device__ float  g_b2 [2 * CH];                          // bias concat bq|bk
__device__ float2 g_part[BATCH * NG * 8];                 // partial {sum, ssq}
__device__ unsigned long long g_rsum[BATCH * HW];         // fixed-point rowsums

// ---------------------------------------------------------------------------
// helpers
// ---------------------------------------------------------------------------
__device__ __forceinline__ uint32_t smem_u32(const void* p) {
    uint32_t a;
    asm("{ .reg .u64 t; cvta.to.shared.u64 t, %1; cvt.u32.u64 %0, t; }"
        : "=r"(a) : "l"(p));
    return a;
}
__device__ __forceinline__ uint32_t pack_hf2(float a, float b) {
    __half2 h = __floats2half2_rn(a, b);
    return *(uint32_t*)&h;
}
#define CP_ASYNC16(saddr, gaddr) \
    asm volatile("cp.async.cg.shared.global [%0], [%1], 16;" \
                 :: "r"(saddr), "l"(gaddr) : "memory")
#define CP_COMMIT() asm volatile("cp.async.commit_group;" ::: "memory")
#define CP_WAIT4()  asm volatile("cp.async.wait_group 4;"  ::: "memory")

#define LDSM4(r0, r1, r2, r3, addr) \
    asm volatile("ldmatrix.sync.aligned.m8n8.x4.shared.b16 {%0,%1,%2,%3}, [%4];" \
                 : "=r"(r0), "=r"(r1), "=r"(r2), "=r"(r3) : "r"(addr))

__device__ __forceinline__ void mma16(float (&d)[4], const uint32_t (&a)[4],
                                      const uint32_t (&b)[2]) {
    asm volatile(
        "mma.sync.aligned.m16n8k16.row.col.f32.f16.f16.f32 "
        "{%0,%1,%2,%3}, {%4,%5,%6,%7}, {%8,%9}, {%0,%1,%2,%3};"
        : "+f"(d[0]), "+f"(d[1]), "+f"(d[2]), "+f"(d[3])
        : "r"(a[0]), "r"(a[1]), "r"(a[2]), "r"(a[3]), "r"(b[0]), "r"(b[1]));
}

// ---- 6-stage swizzled smem: 64B rows, chunk' = chunk ^ ((row>>1)&3) ------
#define NST 6
#define SOP 8192                 // 128 rows * 64 B, per operand per stage

__device__ __forceinline__ void ldsm_set(
    const uint32_t (&aaddr)[4], const uint32_t (&baddr)[4],
    uint32_t ak, uint32_t bk, uint32_t stg,
    uint32_t (&af)[4][4], uint32_t (&bf)[8][2])
{
#pragma unroll
    for (int mt = 0; mt < 4; mt++)
        LDSM4(af[mt][0], af[mt][1], af[mt][2], af[mt][3], aaddr[mt] + stg + ak);
#pragma unroll
    for (int h = 0; h < 4; h++)
        LDSM4(bf[2*h][0], bf[2*h][1], bf[2*h+1][0], bf[2*h+1][1],
              baddr[h] + stg + bk);
}
__device__ __forceinline__ void mma_all(float (&acc)[4][8][4],
                                        const uint32_t (&af)[4][4],
                                        const uint32_t (&bf)[8][2]) {
#pragma unroll
    for (int mt = 0; mt < 4; mt++)
#pragma unroll
        for (int nt = 0; nt < 8; nt++)
            mma16(acc[mt][nt], af[mt], bf[nt]);
}

// ---------------------------------------------------------------------------
// Pre-convert weights to fp16 (q,k,v,o) and concat bq|bk
// ---------------------------------------------------------------------------
__global__ __launch_bounds__(256) void prep_kernel(
    const float* __restrict__ w0, const float* __restrict__ w1,
    const float* __restrict__ w2, const float* __restrict__ w3,
    const float* __restrict__ bq, const float* __restrict__ bk,
    fp16* __restrict__ out, float* __restrict__ b2)
{
    const int n4 = CH * CH / 4;
    const int gid = blockIdx.x * 256 + threadIdx.x;
    const int stride = gridDim.x * 256;
    for (int i = gid; i < 4 * n4; i += stride) {
        const int m = i / n4, j = i - m * n4;
        const float* src = (m == 0) ? w0 : (m == 1) ? w1 : (m == 2) ? w2 : w3;
        float4 v = ((const float4*)src)[j];
        uint2 w;
        w.x = pack_hf2(v.x, v.y);
        w.y = pack_hf2(v.z, v.w);
        ((uint2*)out)[i] = w;
    }
    for (int i = gid; i < 2 * CH; i += stride)
        b2[i] = (i < CH) ? bq[i] : bk[i - CH];
}

// ---------------------------------------------------------------------------
// GroupNorm partial stats: grid (NG, 8 slices, BATCH) -> 512 CTAs (full BW)
// partial[(b*NG+g)*8+s] = {sum, ssq} over 16ch x 512px slice
// ---------------------------------------------------------------------------
__global__ __launch_bounds__(256) void gn_stats_part(
    const float* __restrict__ x, float2* __restrict__ part)
{
    const int g = blockIdx.x, sl = blockIdx.y, b = blockIdx.z;
    const size_t base = ((size_t)b * CH + g * CPG) * HW + sl * 512;

    float s = 0.f, ss = 0.f;
    // 16 ch x 512 px = 2048 float4
    for (int i = threadIdx.x; i < 2048; i += 256) {
        const int ch = i >> 7, p4 = i & 127;
        const float4 v = *(const float4*)&x[base + (size_t)ch * HW + p4 * 4];
        s  += v.x + v.y + v.z + v.w;
        ss += v.x*v.x + v.y*v.y + v.z*v.z + v.w*v.w;
    }
    for (int o = 16; o; o >>= 1) {
        s  += __shfl_xor_sync(0xffffffffu, s,  o);
        ss += __shfl_xor_sync(0xffffffffu, ss, o);
    }
    __shared__ float sw[8], sw2[8];
    const int warp = threadIdx.x >> 5, lane = threadIdx.x & 31;
    if (lane == 0) { sw[warp] = s; sw2[warp] = ss; }
    __syncthreads();
    if (threadIdx.x == 0) {
        float ts = 0.f, tss = 0.f;
#pragma unroll
        for (int i = 0; i < 8; i++) { ts += sw[i]; tss += sw2[i]; }
        part[((size_t)b * NG + g) * 8 + sl] = make_float2(ts, tss);
    }
}

// ---------------------------------------------------------------------------
// Fused GroupNorm-apply + transpose: x [C, HW] fp32 -> hnt [HW, C] fp16
// (combines the 8 slice-partials per group inline)
// ---------------------------------------------------------------------------
__global__ __launch_bounds__(256) void gn_apply_transpose(
    const float* __restrict__ x, const float2* __restrict__ part,
    const float* __restrict__ gamma, const float* __restrict__ beta,
    fp16* __restrict__ out)
{
    __shared__ float tile[32][33];
    const int b = blockIdx.z;
    x   += (size_t)b * CH * HW;
    out += (size_t)b * CH * HW;
    const int p0 = blockIdx.x * 32, c0 = blockIdx.y * 32;
    const int tx = threadIdx.x & 31, ty = threadIdx.x >> 5;
#pragma unroll
    for (int i = 0; i < 32; i += 8)
        tile[ty + i][tx] = x[(size_t)(c0 + ty + i) * HW + p0 + tx];
    __syncthreads();
    const int c = c0 + tx;
    const int g = c >> 4;
    float s = 0.f, ss = 0.f;
#pragma unroll
    for (int sl = 0; sl < 8; sl++) {
        const float2 p = part[((size_t)b * NG + g) * 8 + sl];
        s += p.x; ss += p.y;
    }
    const float n = (float)(CPG * HW);
    const float mean = s / n;
    const float inv = rsqrtf(ss / n - mean * mean + EPSV);
    const float sc = inv * gamma[c];
    const float sh = beta[c] - mean * sc;
#pragma unroll
    for (int i = 0; i < 32; i += 8)
        out[(size_t)(p0 + ty + i) * CH + c] =
            __float2half_rn(tile[tx][ty + i] * sc + sh);
}

// ---------------------------------------------------------------------------
// fp16 mma.sync GEMM: D = f(scale * A(M,K) . B(N,K)^T)  (+epilogue)
// MODE: 0=scale only, 1=+bias[n], 2=+bias[m], 3=+bias[m]+res[m,n] (fp32 out),
//       4=exp2(acc*scale) + per-row fixed-point rowsum atomics,
//       5=acc/rowsum[m] (rowsum = u64 fixed-point via `bias` pointer)
// OT:   0 -> fp32 output, 1 -> fp16 output
// 128x128 CTA tile, BK=32, 6-stage cp.async ring (wait_group 4), 128 threads
// (4 warps 2x2, warp tile 64x64), XOR-swizzled 64B-row smem, frag dbl-buffer.
// ---------------------------------------------------------------------------
#define FIXP 1048576.0f              // 2^20 fixed-point scale for rowsums
template<int MODE, int OT>
__global__ __launch_bounds__(128, 2) void bgemm(
    const fp16* __restrict__ A, const fp16* __restrict__ B,
    void* __restrict__ Cv,
    const float* __restrict__ bias, const float* __restrict__ res,
    int K, int lda, int ldb, int ldc,
    long long sA, long long sB, long long sC, float scale,
    unsigned long long* rsum)
{
    extern __shared__ char sm[];
    const uint32_t Abase = smem_u32(sm);
    const uint32_t Bbase = Abase + NST * SOP;

    const int tid = threadIdx.x, lane = tid & 31, wid = tid >> 5;
    const int wm = wid & 1, wn = wid >> 1;          // warp grid 2m x 2n
    const int grp = lane >> 2, tig = lane & 3;
    const int bz = blockIdx.z;
    A += bz * sA; B += bz * sB;
    const float* resb = (MODE == 3) ? res + bz * sC : nullptr;
    const unsigned long long* rsb =
        (MODE == 5) ? (const unsigned long long*)bias + (size_t)bz * HW : nullptr;
    const int m0 = blockIdx.y * 128, n0 = blockIdx.x * 128;

    const int lr = tid >> 2;
    const int c  = tid & 3;
    const int cx = c ^ ((lr >> 1) & 3);             // swizzled chunk
    const fp16* Ag = A + (size_t)(m0 + lr) * lda + c * 8;
    const fp16* Bg = B + (size_t)(n0 + lr) * ldb + c * 8;
    const uint32_t sa0 = Abase + (uint32_t)(lr * 64 + cx * 16);
    const uint32_t sb0 = Bbase + (uint32_t)(lr * 64 + cx * 16);
    const uint32_t r32 = 32 * 64;

    const uint32_t la_row = lane & 15;
    uint32_t aaddr[4];
#pragma unroll
    for (int mt = 0; mt < 4; mt++)
        aaddr[mt] = Abase + (uint32_t)((wm * 64 + mt * 16 + la_row) * 64);
    const uint32_t acb = lane >> 4;
    const uint32_t axa = (la_row >> 1) & 3;
    const uint32_t akoff[2] = { ((acb    ) ^ axa) * 16, ((acb + 2) ^ axa) * 16 };

    const uint32_t lb_row = ((lane >> 4) * 8) + (lane & 7);
    uint32_t baddr[4];
#pragma unroll
    for (int h = 0; h < 4; h++)
        baddr[h] = Bbase + (uint32_t)((wn * 64 + h * 16 + lb_row) * 64);
    const uint32_t bcb = (lane >> 3) & 1;
    const uint32_t bxa = (lb_row >> 1) & 3;
    const uint32_t bkoff[2] = { ((bcb    ) ^ bxa) * 16, ((bcb + 2) ^ bxa) * 16 };

    float acc[4][8][4];
#pragma unroll
    for (int mt = 0; mt < 4; mt++)
#pragma unroll
        for (int nt = 0; nt < 8; nt++)
#pragma unroll
            for (int j = 0; j < 4; j++) acc[mt][nt][j] = 0.f;

    const int T = K >> 5;

    // prologue: stages 0..4
#pragma unroll
    for (int p = 0; p < 5; p++) {
        const size_t ko = (size_t)p * 32;
        const uint32_t st = p * SOP;
#pragma unroll
        for (int h = 0; h < 4; h++) {
            CP_ASYNC16(sa0 + st + h * r32, Ag + (size_t)h * 32 * lda + ko);
            CP_ASYNC16(sb0 + st + h * r32, Bg + (size_t)h * 32 * ldb + ko);
        }
        CP_COMMIT();
    }
    CP_WAIT4();
    __syncthreads();

    uint32_t af[2][4][4], bfr[2][8][2];
    ldsm_set(aaddr, baddr, akoff[0], bkoff[0], 0, af[0], bfr[0]);

    int cur = 0;
    for (int kt = 0; kt < T; kt++) {
        const uint32_t so = cur * SOP;
        ldsm_set(aaddr, baddr, akoff[1], bkoff[1], so, af[1], bfr[1]);
        mma_all(acc, af[0], bfr[0]);

        if (kt + 5 < T) {
            const size_t ko = (size_t)(kt + 5) * 32;
            const int slot = (kt + 5) % NST;
            const uint32_t st = slot * SOP;
#pragma unroll
            for (int h = 0; h < 4; h++) {
                CP_ASYNC16(sa0 + st + h * r32, Ag + (size_t)h * 32 * lda + ko);
                CP_ASYNC16(sb0 + st + h * r32, Bg + (size_t)h * 32 * ldb + ko);
            }
        }
        CP_COMMIT();

        const int nstage = (cur + 1 == NST) ? 0 : cur + 1;
        if (kt + 1 < T) {
            CP_WAIT4();
            __syncthreads();
            ldsm_set(aaddr, baddr, akoff[0], bkoff[0], nstage * SOP,
                     af[0], bfr[0]);
        }
        mma_all(acc, af[1], bfr[1]);
        cur = nstage;
    }

    // Epilogue
    float* Cf = (float*)Cv + ((OT == 0) ? bz * sC : 0);
    fp16*  Ch = (fp16*)Cv  + ((OT == 1) ? bz * sC : 0);
#pragma unroll
    for (int mt = 0; mt < 4; mt++) {
        const int r0 = m0 + wm * 64 + mt * 16 + grp;
        float bm0 = 0.f, bm1 = 0.f;
        if (MODE == 2 || MODE == 3) { bm0 = bias[r0]; bm1 = bias[r0 + 8]; }
        if (MODE == 5) {
            bm0 = FIXP / (float)rsb[r0];
            bm1 = FIXP / (float)rsb[r0 + 8];
        }
        float rs0 = 0.f, rs1 = 0.f;      // MODE 4 per-row partials
#pragma unroll
        for (int nt = 0; nt < 8; nt++) {
            const int cc = n0 + wn * 64 + nt * 8 + tig * 2;
            const float* d = acc[mt][nt];
            float2 o0, o1;
            if (MODE == 4) {
                o0.x = exp2f(d[0] * scale); o0.y = exp2f(d[1] * scale);
                o1.x = exp2f(d[2] * scale); o1.y = exp2f(d[3] * scale);
                rs0 += o0.x + o0.y;
                rs1 += o1.x + o1.y;
            } else if (MODE == 5) {
                o0.x = d[0] * bm0; o0.y = d[1] * bm0;
                o1.x = d[2] * bm1; o1.y = d[3] * bm1;
            } else {
                o0.x = d[0] * scale; o0.y = d[1] * scale;
                o1.x = d[2] * scale; o1.y = d[3] * scale;
                if (MODE == 1) {
                    const float2 bn = *(const float2*)&bias[cc];
                    o0.x += bn.x; o0.y += bn.y; o1.x += bn.x; o1.y += bn.y;
                }
                if (MODE == 2 || MODE == 3) {
                    o0.x += bm0; o0.y += bm0; o1.x += bm1; o1.y += bm1;
                }
            }
            const size_t i0 = (size_t)r0 * ldc + cc;
            const size_t i1 = (size_t)(r0 + 8) * ldc + cc;
            if (MODE == 3) {
                const float2 r0v = *(const float2*)&resb[i0];
                const float2 r1v = *(const float2*)&resb[i1];
                o0.x += r0v.x; o0.y += r0v.y; o1.x += r1v.x; o1.y += r1v.y;
            }
            if (OT == 0) {
                *(float2*)&Cf[i0] = o0;
                *(float2*)&Cf[i1] = o1;
            } else {
                *(uint32_t*)&Ch[i0] = pack_hf2(o0.x, o0.y);
                *(uint32_t*)&Ch[i1] = pack_hf2(o1.x, o1.y);
            }
        }
        if (MODE == 4) {
            // reduce across the 4-lane tig group (same rows, different cols)
            rs0 += __shfl_xor_sync(0xffffffffu, rs0, 1);
            rs0 += __shfl_xor_sync(0xffffffffu, rs0, 2);
            rs1 += __shfl_xor_sync(0xffffffffu, rs1, 1);
            rs1 += __shfl_xor_sync(0xffffffffu, rs1, 2);
            if (tig == 0) {
                atomicAdd(&rsum[(size_t)bz * HW + r0],
                          __float2ull_rn(rs0 * FIXP));
                atomicAdd(&rsum[(size_t)bz * HW + r0 + 8],
                          __float2ull_rn(rs1 * FIXP));
            }
        }
    }
}

// ---------------------------------------------------------------------------
extern "C" void kernel_launch(void* const* d_in, const int* in_sizes, int n_in,
                              void* d_out, int out_size)
{
    const float* x     = (const float*)d_in[0];
    const float* gamma = (const float*)d_in[1];
    const float* beta  = (const float*)d_in[2];
    const float* wq    = (const float*)d_in[3];
    const float* bq    = (const float*)d_in[4];
    const float* wk    = (const float*)d_in[5];
    const float* bk    = (const float*)d_in[6];
    const float* wv    = (const float*)d_in[7];
    const float* bv    = (const float*)d_in[8];
    const float* wo    = (const float*)d_in[9];
    const float* bo    = (const float*)d_in[10];
    float* out = (float*)d_out;

    float *b2;
    float2* part;
    unsigned long long* rsum;
    fp16 *hnt, *qk, *v, *aot, *es, *wb;
    cudaGetSymbolAddress((void**)&hnt,  g_hnt);
    cudaGetSymbolAddress((void**)&qk,   g_qk);
    cudaGetSymbolAddress((void**)&v,    g_v);
    cudaGetSymbolAddress((void**)&aot,  g_aot);
    cudaGetSymbolAddress((void**)&es,   g_es);
    cudaGetSymbolAddress((void**)&wb,   g_wb);
    cudaGetSymbolAddress((void**)&b2,   g_b2);
    cudaGetSymbolAddress((void**)&part, g_part);
    cudaGetSymbolAddress((void**)&rsum, g_rsum);
    const fp16* wvb = wb + 2 * CH * CH;
    const fp16* wob = wb + 3 * CH * CH;

    const int SMEM = 2 * NST * SOP;   // 98304 B
    static int smem_set = 0;
    if (!smem_set) {
        cudaFuncSetAttribute(bgemm<1,1>, cudaFuncAttributeMaxDynamicSharedMemorySize, SMEM);
        cudaFuncSetAttribute(bgemm<2,1>, cudaFuncAttributeMaxDynamicSharedMemorySize, SMEM);
        cudaFuncSetAttribute(bgemm<4,1>, cudaFuncAttributeMaxDynamicSharedMemorySize, SMEM);
        cudaFuncSetAttribute(bgemm<5,1>, cudaFuncAttributeMaxDynamicSharedMemorySize, SMEM);
        cudaFuncSetAttribute(bgemm<3,0>, cudaFuncAttributeMaxDynamicSharedMemorySize, SMEM);
        smem_set = 1;
    }

    const long long sCH  = (long long)CH * HW;
    const long long sQK  = (long long)HW * 2 * CH;
    const long long sHW  = (long long)HW * HW;
    // exp2 scale: (1/sqrt(512)) * log2(e)
    const float escale = 0.044194173824159216f * 1.4426950408889634f;

    // 0. zero rowsum accumulators (capture-legal async memset node)
    cudaMemsetAsync(rsum, 0, BATCH * HW * sizeof(unsigned long long));
    // 1. weights -> fp16, bias concat
    prep_kernel<<<256, 256>>>(wq, wk, wv, wo, bq, bk, wb, b2);
    // 2. GroupNorm partial stats (512 CTAs, full-chip BW)
    gn_stats_part<<<dim3(NG, 8, BATCH), 256>>>(x, part);
    // 3. fused apply + transpose -> hnt [HW, C] fp16
    gn_apply_transpose<<<dim3(HW / 32, CH / 32, BATCH), 256>>>(
        x, part, gamma, beta, hnt);

    // 4. qk[p, 0:1024] = hnt . [Wq;Wk]^T + [bq;bk]   (M=4096, N=1024, K=512)
    bgemm<1,1><<<dim3(2 * CH / 128, HW / 128, BATCH), 128, SMEM>>>(
        hnt, wb, qk, b2, nullptr, CH, CH, CH, 2 * CH, sCH, 0, sQK, 1.f, nullptr);
    // 5. v[c,p] = Wv . hnt^T + bv[c]                 (M=512, N=4096, K=512)
    bgemm<2,1><<<dim3(HW / 128, CH / 128, BATCH), 128, SMEM>>>(
        wvb, hnt, v, bv, nullptr, CH, CH, CH, HW, 0, sCH, sCH, 1.f, nullptr);

    // 6. es[i,j] = exp(q.k^T * scale), rowsums accumulated in-epilogue
    bgemm<4,1><<<dim3(HW / 128, HW / 128, BATCH), 128, SMEM>>>(
        qk, qk + CH, es, nullptr, nullptr, CH, 2 * CH, 2 * CH, HW,
        sQK, sQK, sHW, escale, rsum);

    // 7. ao_t[i,c] = (es . v^T)[i,c] / rowsum[i]     (M=4096, N=512, K=4096)
    bgemm<5,1><<<dim3(CH / 128, HW / 128, BATCH), 128, SMEM>>>(
        es, v, aot, (const float*)rsum, nullptr, HW, HW, HW, CH,
        sHW, sCH, sCH, 1.f, nullptr);

    // 8. out[o,p] = Wo . ao_t^T + bo[o] + x          (M=512, N=4096, K=512)
    bgemm<3,0><<<dim3(HW / 128, CH / 128, BATCH), 128, SMEM>>>(
        wob, aot, out, bo, x, CH, CH, CH, HW, 0, sCH, sCH, 1.f, nullptr);
}

// round 17
// speedup vs baseline: 1.4032x; 1.0004x over previous
#include <cuda_runtime.h>
#include <cuda_fp16.h>
#include <cstdint>

#define CH 512
#define HW 4096
#define BATCH 2
#define NG 32
#define CPG 16
#define EPSV 1e-6f

typedef __half fp16;

// Scratch (allocation-free rule: __device__ globals)
__device__ fp16   g_hnt[BATCH * CH * HW];                 // [HW, C]
__device__ fp16   g_qk [BATCH * HW * 2 * CH];             // [HW, 1024] q|k
__device__ fp16   g_v  [BATCH * CH * HW];                 // [C, HW]
__device__ fp16   g_aot[BATCH * CH * HW];                 // [HW, C]
__device__ fp16   g_es [(size_t)BATCH * HW * HW];         // fp16 exp-scores
__device__ fp16   g_wb [4 * CH * CH];                     // fp16 weights q,k,v,o
__device__ float  g_b2 [2 * CH];                          // bias concat bq|bk
__device__ float2 g_part[BATCH * NG * 8];                 // partial {sum, ssq}
__device__ unsigned long long g_rsum[BATCH * HW];         // fixed-point rowsums

// ---------------------------------------------------------------------------
// helpers
// ---------------------------------------------------------------------------
__device__ __forceinline__ uint32_t smem_u32(const void* p) {
    uint32_t a;
    asm("{ .reg .u64 t; cvta.to.shared.u64 t, %1; cvt.u32.u64 %0, t; }"
        : "=r"(a) : "l"(p));
    return a;
}
__device__ __forceinline__ uint32_t pack_hf2(float a, float b) {
    __half2 h = __floats2half2_rn(a, b);
    return *(uint32_t*)&h;
}
#define CP_ASYNC16(saddr, gaddr) \
    asm volatile("cp.async.cg.shared.global [%0], [%1], 16;" \
                 :: "r"(saddr), "l"(gaddr) : "memory")
#define CP_COMMIT() asm volatile("cp.async.commit_group;" ::: "memory")
#define CP_WAIT4()  asm volatile("cp.async.wait_group 4;"  ::: "memory")

#define LDSM4(r0, r1, r2, r3, addr) \
    asm volatile("ldmatrix.sync.aligned.m8n8.x4.shared.b16 {%0,%1,%2,%3}, [%4];" \
                 : "=r"(r0), "=r"(r1), "=r"(r2), "=r"(r3) : "r"(addr))

__device__ __forceinline__ void mma16(float (&d)[4], const uint32_t (&a)[4],
                                      const uint32_t (&b)[2]) {
    asm volatile(
        "mma.sync.aligned.m16n8k16.row.col.f32.f16.f16.f32 "
        "{%0,%1,%2,%3}, {%4,%5,%6,%7}, {%8,%9}, {%0,%1,%2,%3};"
        : "+f"(d[0]), "+f"(d[1]), "+f"(d[2]), "+f"(d[3])
        : "r"(a[0]), "r"(a[1]), "r"(a[2]), "r"(a[3]), "r"(b[0]), "r"(b[1]));
}
// fp16-accumulate variant (probe: possibly 2x rate on legacy HMMA path)
__device__ __forceinline__ void mma16h(uint32_t (&d)[2], const uint32_t (&a)[4],
                                       const uint32_t (&b)[2]) {
    asm volatile(
        "mma.sync.aligned.m16n8k16.row.col.f16.f16.f16.f16 "
        "{%0,%1}, {%2,%3,%4,%5}, {%6,%7}, {%0,%1};"
        : "+r"(d[0]), "+r"(d[1])
        : "r"(a[0]), "r"(a[1]), "r"(a[2]), "r"(a[3]), "r"(b[0]), "r"(b[1]));
}

// ---- 6-stage swizzled smem: 64B rows, chunk' = chunk ^ ((row>>1)&3) ------
#define NST 6
#define SOP 8192                 // 128 rows * 64 B, per operand per stage

__device__ __forceinline__ void ldsm_set(
    const uint32_t (&aaddr)[4], const uint32_t (&baddr)[4],
    uint32_t ak, uint32_t bk, uint32_t stg,
    uint32_t (&af)[4][4], uint32_t (&bf)[8][2])
{
#pragma unroll
    for (int mt = 0; mt < 4; mt++)
        LDSM4(af[mt][0], af[mt][1], af[mt][2], af[mt][3], aaddr[mt] + stg + ak);
#pragma unroll
    for (int h = 0; h < 4; h++)
        LDSM4(bf[2*h][0], bf[2*h][1], bf[2*h+1][0], bf[2*h+1][1],
              baddr[h] + stg + bk);
}
__device__ __forceinline__ void mma_all(float (&acc)[4][8][4],
                                        const uint32_t (&af)[4][4],
                                        const uint32_t (&bf)[8][2]) {
#pragma unroll
    for (int mt = 0; mt < 4; mt++)
#pragma unroll
        for (int nt = 0; nt < 8; nt++)
            mma16(acc[mt][nt], af[mt], bf[nt]);
}
__device__ __forceinline__ void mma_all_h(uint32_t (&acc)[4][8][2],
                                          const uint32_t (&af)[4][4],
                                          const uint32_t (&bf)[8][2]) {
#pragma unroll
    for (int mt = 0; mt < 4; mt++)
#pragma unroll
        for (int nt = 0; nt < 8; nt++)
            mma16h(acc[mt][nt], af[mt], bf[nt]);
}

// ---------------------------------------------------------------------------
// Pre-convert weights to fp16 (q,k,v,o) and concat bq|bk
// ---------------------------------------------------------------------------
__global__ __launch_bounds__(256) void prep_kernel(
    const float* __restrict__ w0, const float* __restrict__ w1,
    const float* __restrict__ w2, const float* __restrict__ w3,
    const float* __restrict__ bq, const float* __restrict__ bk,
    fp16* __restrict__ out, float* __restrict__ b2)
{
    const int n4 = CH * CH / 4;
    const int gid = blockIdx.x * 256 + threadIdx.x;
    const int stride = gridDim.x * 256;
    for (int i = gid; i < 4 * n4; i += stride) {
        const int m = i / n4, j = i - m * n4;
        const float* src = (m == 0) ? w0 : (m == 1) ? w1 : (m == 2) ? w2 : w3;
        float4 v = ((const float4*)src)[j];
        uint2 w;
        w.x = pack_hf2(v.x, v.y);
        w.y = pack_hf2(v.z, v.w);
        ((uint2*)out)[i] = w;
    }
    for (int i = gid; i < 2 * CH; i += stride)
        b2[i] = (i < CH) ? bq[i] : bk[i - CH];
}

// ---------------------------------------------------------------------------
// GroupNorm partial stats: grid (NG, 8 slices, BATCH) -> 512 CTAs (full BW)
// ---------------------------------------------------------------------------
__global__ __launch_bounds__(256) void gn_stats_part(
    const float* __restrict__ x, float2* __restrict__ part)
{
    const int g = blockIdx.x, sl = blockIdx.y, b = blockIdx.z;
    const size_t base = ((size_t)b * CH + g * CPG) * HW + sl * 512;

    float s = 0.f, ss = 0.f;
    for (int i = threadIdx.x; i < 2048; i += 256) {
        const int ch = i >> 7, p4 = i & 127;
        const float4 v = *(const float4*)&x[base + (size_t)ch * HW + p4 * 4];
        s  += v.x + v.y + v.z + v.w;
        ss += v.x*v.x + v.y*v.y + v.z*v.z + v.w*v.w;
    }
    for (int o = 16; o; o >>= 1) {
        s  += __shfl_xor_sync(0xffffffffu, s,  o);
        ss += __shfl_xor_sync(0xffffffffu, ss, o);
    }
    __shared__ float sw[8], sw2[8];
    const int warp = threadIdx.x >> 5, lane = threadIdx.x & 31;
    if (lane == 0) { sw[warp] = s; sw2[warp] = ss; }
    __syncthreads();
    if (threadIdx.x == 0) {
        float ts = 0.f, tss = 0.f;
#pragma unroll
        for (int i = 0; i < 8; i++) { ts += sw[i]; tss += sw2[i]; }
        part[((size_t)b * NG + g) * 8 + sl] = make_float2(ts, tss);
    }
}

// ---------------------------------------------------------------------------
// Fused GroupNorm-apply + transpose: x [C, HW] fp32 -> hnt [HW, C] fp16
// ---------------------------------------------------------------------------
__global__ __launch_bounds__(256) void gn_apply_transpose(
    const float* __restrict__ x, const float2* __restrict__ part,
    const float* __restrict__ gamma, const float* __restrict__ beta,
    fp16* __restrict__ out)
{
    __shared__ float tile[32][33];
    const int b = blockIdx.z;
    x   += (size_t)b * CH * HW;
    out += (size_t)b * CH * HW;
    const int p0 = blockIdx.x * 32, c0 = blockIdx.y * 32;
    const int tx = threadIdx.x & 31, ty = threadIdx.x >> 5;
#pragma unroll
    for (int i = 0; i < 32; i += 8)
        tile[ty + i][tx] = x[(size_t)(c0 + ty + i) * HW + p0 + tx];
    __syncthreads();
    const int c = c0 + tx;
    const int g = c >> 4;
    float s = 0.f, ss = 0.f;
#pragma unroll
    for (int sl = 0; sl < 8; sl++) {
        const float2 p = part[((size_t)b * NG + g) * 8 + sl];
        s += p.x; ss += p.y;
    }
    const float n = (float)(CPG * HW);
    const float mean = s / n;
    const float inv = rsqrtf(ss / n - mean * mean + EPSV);
    const float sc = inv * gamma[c];
    const float sh = beta[c] - mean * sc;
#pragma unroll
    for (int i = 0; i < 32; i += 8)
        out[(size_t)(p0 + ty + i) * CH + c] =
            __float2half_rn(tile[tx][ty + i] * sc + sh);
}

// ---------------------------------------------------------------------------
// fp16 mma.sync GEMM (fp32 acc): D = f(scale * A . B^T)  (+epilogue)
// MODE: 0=scale, 1=+bias[n], 2=+bias[m], 3=+bias[m]+res (fp32 out),
//       5=acc/rowsum[m] (u64 fixed-point via `bias`)
// OT:   0 -> fp32 output, 1 -> fp16 output
// ---------------------------------------------------------------------------
#define FIXP 1048576.0f              // 2^20 fixed-point scale for rowsums
template<int MODE, int OT>
__global__ __launch_bounds__(128, 2) void bgemm(
    const fp16* __restrict__ A, const fp16* __restrict__ B,
    void* __restrict__ Cv,
    const float* __restrict__ bias, const float* __restrict__ res,
    int K, int lda, int ldb, int ldc,
    long long sA, long long sB, long long sC, float scale)
{
    extern __shared__ char sm[];
    const uint32_t Abase = smem_u32(sm);
    const uint32_t Bbase = Abase + NST * SOP;

    const int tid = threadIdx.x, lane = tid & 31, wid = tid >> 5;
    const int wm = wid & 1, wn = wid >> 1;
    const int grp = lane >> 2, tig = lane & 3;
    const int bz = blockIdx.z;
    A += bz * sA; B += bz * sB;
    const float* resb = (MODE == 3) ? res + bz * sC : nullptr;
    const unsigned long long* rsb =
        (MODE == 5) ? (const unsigned long long*)bias + (size_t)bz * HW : nullptr;
    const int m0 = blockIdx.y * 128, n0 = blockIdx.x * 128;

    const int lr = tid >> 2;
    const int c  = tid & 3;
    const int cx = c ^ ((lr >> 1) & 3);
    const fp16* Ag = A + (size_t)(m0 + lr) * lda + c * 8;
    const fp16* Bg = B + (size_t)(n0 + lr) * ldb + c * 8;
    const uint32_t sa0 = Abase + (uint32_t)(lr * 64 + cx * 16);
    const uint32_t sb0 = Bbase + (uint32_t)(lr * 64 + cx * 16);
    const uint32_t r32 = 32 * 64;

    const uint32_t la_row = lane & 15;
    uint32_t aaddr[4];
#pragma unroll
    for (int mt = 0; mt < 4; mt++)
        aaddr[mt] = Abase + (uint32_t)((wm * 64 + mt * 16 + la_row) * 64);
    const uint32_t acb = lane >> 4;
    const uint32_t axa = (la_row >> 1) & 3;
    const uint32_t akoff[2] = { ((acb    ) ^ axa) * 16, ((acb + 2) ^ axa) * 16 };

    const uint32_t lb_row = ((lane >> 4) * 8) + (lane & 7);
    uint32_t baddr[4];
#pragma unroll
    for (int h = 0; h < 4; h++)
        baddr[h] = Bbase + (uint32_t)((wn * 64 + h * 16 + lb_row) * 64);
    const uint32_t bcb = (lane >> 3) & 1;
    const uint32_t bxa = (lb_row >> 1) & 3;
    const uint32_t bkoff[2] = { ((bcb    ) ^ bxa) * 16, ((bcb + 2) ^ bxa) * 16 };

    float acc[4][8][4];
#pragma unroll
    for (int mt = 0; mt < 4; mt++)
#pragma unroll
        for (int nt = 0; nt < 8; nt++)
#pragma unroll
            for (int j = 0; j < 4; j++) acc[mt][nt][j] = 0.f;

    const int T = K >> 5;

#pragma unroll
    for (int p = 0; p < 5; p++) {
        const size_t ko = (size_t)p * 32;
        const uint32_t st = p * SOP;
#pragma unroll
        for (int h = 0; h < 4; h++) {
            CP_ASYNC16(sa0 + st + h * r32, Ag + (size_t)h * 32 * lda + ko);
            CP_ASYNC16(sb0 + st + h * r32, Bg + (size_t)h * 32 * ldb + ko);
        }
        CP_COMMIT();
    }
    CP_WAIT4();
    __syncthreads();

    uint32_t af[2][4][4], bfr[2][8][2];
    ldsm_set(aaddr, baddr, akoff[0], bkoff[0], 0, af[0], bfr[0]);

    int cur = 0;
    for (int kt = 0; kt < T; kt++) {
        const uint32_t so = cur * SOP;
        ldsm_set(aaddr, baddr, akoff[1], bkoff[1], so, af[1], bfr[1]);
        mma_all(acc, af[0], bfr[0]);

        if (kt + 5 < T) {
            const size_t ko = (size_t)(kt + 5) * 32;
            const int slot = (kt + 5) % NST;
            const uint32_t st = slot * SOP;
#pragma unroll
            for (int h = 0; h < 4; h++) {
                CP_ASYNC16(sa0 + st + h * r32, Ag + (size_t)h * 32 * lda + ko);
                CP_ASYNC16(sb0 + st + h * r32, Bg + (size_t)h * 32 * ldb + ko);
            }
        }
        CP_COMMIT();

        const int nstage = (cur + 1 == NST) ? 0 : cur + 1;
        if (kt + 1 < T) {
            CP_WAIT4();
            __syncthreads();
            ldsm_set(aaddr, baddr, akoff[0], bkoff[0], nstage * SOP,
                     af[0], bfr[0]);
        }
        mma_all(acc, af[1], bfr[1]);
        cur = nstage;
    }

    // Epilogue
    float* Cf = (float*)Cv + ((OT == 0) ? bz * sC : 0);
    fp16*  Ch = (fp16*)Cv  + ((OT == 1) ? bz * sC : 0);
#pragma unroll
    for (int mt = 0; mt < 4; mt++) {
        const int r0 = m0 + wm * 64 + mt * 16 + grp;
        float bm0 = 0.f, bm1 = 0.f;
        if (MODE == 2 || MODE == 3) { bm0 = bias[r0]; bm1 = bias[r0 + 8]; }
        if (MODE == 5) {
            bm0 = FIXP / (float)rsb[r0];
            bm1 = FIXP / (float)rsb[r0 + 8];
        }
#pragma unroll
        for (int nt = 0; nt < 8; nt++) {
            const int cc = n0 + wn * 64 + nt * 8 + tig * 2;
            const float* d = acc[mt][nt];
            float2 o0, o1;
            if (MODE == 5) {
                o0.x = d[0] * bm0; o0.y = d[1] * bm0;
                o1.x = d[2] * bm1; o1.y = d[3] * bm1;
            } else {
                o0.x = d[0] * scale; o0.y = d[1] * scale;
                o1.x = d[2] * scale; o1.y = d[3] * scale;
                if (MODE == 1) {
                    const float2 bn = *(const float2*)&bias[cc];
                    o0.x += bn.x; o0.y += bn.y; o1.x += bn.x; o1.y += bn.y;
                }
                if (MODE == 2 || MODE == 3) {
                    o0.x += bm0; o0.y += bm0; o1.x += bm1; o1.y += bm1;
                }
            }
            const size_t i0 = (size_t)r0 * ldc + cc;
            const size_t i1 = (size_t)(r0 + 8) * ldc + cc;
            if (MODE == 3) {
                const float2 r0v = *(const float2*)&resb[i0];
                const float2 r1v = *(const float2*)&resb[i1];
                o0.x += r0v.x; o0.y += r0v.y; o1.x += r1v.x; o1.y += r1v.y;
            }
            if (OT == 0) {
                *(float2*)&Cf[i0] = o0;
                *(float2*)&Cf[i1] = o1;
            } else {
                *(uint32_t*)&Ch[i0] = pack_hf2(o0.x, o0.y);
                *(uint32_t*)&Ch[i1] = pack_hf2(o1.x, o1.y);
            }
        }
    }
}

// ---------------------------------------------------------------------------
// Scores GEMM, fp16 accumulate (rate probe): es = exp2(acc * escale), fp16
// out, per-row fixed-point rowsum atomics. Same pipeline as bgemm.
// ---------------------------------------------------------------------------
__global__ __launch_bounds__(128, 2) void sgemm_exp(
    const fp16* __restrict__ A, const fp16* __restrict__ B,
    fp16* __restrict__ Cv,
    int K, int lda, int ldb, int ldc,
    long long sA, long long sB, long long sC, float scale,
    unsigned long long* rsum)
{
    extern __shared__ char sm[];
    const uint32_t Abase = smem_u32(sm);
    const uint32_t Bbase = Abase + NST * SOP;

    const int tid = threadIdx.x, lane = tid & 31, wid = tid >> 5;
    const int wm = wid & 1, wn = wid >> 1;
    const int grp = lane >> 2, tig = lane & 3;
    const int bz = blockIdx.z;
    A += bz * sA; B += bz * sB;
    fp16* Cb = Cv + bz * sC;
    const int m0 = blockIdx.y * 128, n0 = blockIdx.x * 128;

    const int lr = tid >> 2;
    const int c  = tid & 3;
    const int cx = c ^ ((lr >> 1) & 3);
    const fp16* Ag = A + (size_t)(m0 + lr) * lda + c * 8;
    const fp16* Bg = B + (size_t)(n0 + lr) * ldb + c * 8;
    const uint32_t sa0 = Abase + (uint32_t)(lr * 64 + cx * 16);
    const uint32_t sb0 = Bbase + (uint32_t)(lr * 64 + cx * 16);
    const uint32_t r32 = 32 * 64;

    const uint32_t la_row = lane & 15;
    uint32_t aaddr[4];
#pragma unroll
    for (int mt = 0; mt < 4; mt++)
        aaddr[mt] = Abase + (uint32_t)((wm * 64 + mt * 16 + la_row) * 64);
    const uint32_t acb = lane >> 4;
    const uint32_t axa = (la_row >> 1) & 3;
    const uint32_t akoff[2] = { ((acb    ) ^ axa) * 16, ((acb + 2) ^ axa) * 16 };

    const uint32_t lb_row = ((lane >> 4) * 8) + (lane & 7);
    uint32_t baddr[4];
#pragma unroll
    for (int h = 0; h < 4; h++)
        baddr[h] = Bbase + (uint32_t)((wn * 64 + h * 16 + lb_row) * 64);
    const uint32_t bcb = (lane >> 3) & 1;
    const uint32_t bxa = (lb_row >> 1) & 3;
    const uint32_t bkoff[2] = { ((bcb    ) ^ bxa) * 16, ((bcb + 2) ^ bxa) * 16 };

    uint32_t acc[4][8][2];               // fp16x2 accumulators
#pragma unroll
    for (int mt = 0; mt < 4; mt++)
#pragma unroll
        for (int nt = 0; nt < 8; nt++) { acc[mt][nt][0] = 0u; acc[mt][nt][1] = 0u; }

    const int T = K >> 5;

#pragma unroll
    for (int p = 0; p < 5; p++) {
        const size_t ko = (size_t)p * 32;
        const uint32_t st = p * SOP;
#pragma unroll
        for (int h = 0; h < 4; h++) {
            CP_ASYNC16(sa0 + st + h * r32, Ag + (size_t)h * 32 * lda + ko);
            CP_ASYNC16(sb0 + st + h * r32, Bg + (size_t)h * 32 * ldb + ko);
        }
        CP_COMMIT();
    }
    CP_WAIT4();
    __syncthreads();

    uint32_t af[2][4][4], bfr[2][8][2];
    ldsm_set(aaddr, baddr, akoff[0], bkoff[0], 0, af[0], bfr[0]);

    int cur = 0;
    for (int kt = 0; kt < T; kt++) {
        const uint32_t so = cur * SOP;
        ldsm_set(aaddr, baddr, akoff[1], bkoff[1], so, af[1], bfr[1]);
        mma_all_h(acc, af[0], bfr[0]);

        if (kt + 5 < T) {
            const size_t ko = (size_t)(kt + 5) * 32;
            const int slot = (kt + 5) % NST;
            const uint32_t st = slot * SOP;
#pragma unroll
            for (int h = 0; h < 4; h++) {
                CP_ASYNC16(sa0 + st + h * r32, Ag + (size_t)h * 32 * lda + ko);
                CP_ASYNC16(sb0 + st + h * r32, Bg + (size_t)h * 32 * ldb + ko);
            }
        }
        CP_COMMIT();

        const int nstage = (cur + 1 == NST) ? 0 : cur + 1;
        if (kt + 1 < T) {
            CP_WAIT4();
            __syncthreads();
            ldsm_set(aaddr, baddr, akoff[0], bkoff[0], nstage * SOP,
                     af[0], bfr[0]);
        }
        mma_all_h(acc, af[1], bfr[1]);
        cur = nstage;
    }

    // Epilogue: exp2(acc * scale) -> fp16 store + fixed-point rowsums
#pragma unroll
    for (int mt = 0; mt < 4; mt++) {
        const int r0 = m0 + wm * 64 + mt * 16 + grp;
        float rs0 = 0.f, rs1 = 0.f;
#pragma unroll
        for (int nt = 0; nt < 8; nt++) {
            const int cc = n0 + wn * 64 + nt * 8 + tig * 2;
            const float2 d0 = __half22float2(*(const __half2*)&acc[mt][nt][0]);
            const float2 d1 = __half22float2(*(const __half2*)&acc[mt][nt][1]);
            float2 o0, o1;
            o0.x = exp2f(d0.x * scale); o0.y = exp2f(d0.y * scale);
            o1.x = exp2f(d1.x * scale); o1.y = exp2f(d1.y * scale);
            rs0 += o0.x + o0.y;
            rs1 += o1.x + o1.y;
            const size_t i0 = (size_t)r0 * ldc + cc;
            const size_t i1 = (size_t)(r0 + 8) * ldc + cc;
            *(uint32_t*)&Cb[i0] = pack_hf2(o0.x, o0.y);
            *(uint32_t*)&Cb[i1] = pack_hf2(o1.x, o1.y);
        }
        rs0 += __shfl_xor_sync(0xffffffffu, rs0, 1);
        rs0 += __shfl_xor_sync(0xffffffffu, rs0, 2);
        rs1 += __shfl_xor_sync(0xffffffffu, rs1, 1);
        rs1 += __shfl_xor_sync(0xffffffffu, rs1, 2);
        if (tig == 0) {
            atomicAdd(&rsum[(size_t)bz * HW + r0],     __float2ull_rn(rs0 * FIXP));
            atomicAdd(&rsum[(size_t)bz * HW + r0 + 8], __float2ull_rn(rs1 * FIXP));
        }
    }
}

// ---------------------------------------------------------------------------
extern "C" void kernel_launch(void* const* d_in, const int* in_sizes, int n_in,
                              void* d_out, int out_size)
{
    const float* x     = (const float*)d_in[0];
    const float* gamma = (const float*)d_in[1];
    const float* beta  = (const float*)d_in[2];
    const float* wq    = (const float*)d_in[3];
    const float* bq    = (const float*)d_in[4];
    const float* wk    = (const float*)d_in[5];
    const float* bk    = (const float*)d_in[6];
    const float* wv    = (const float*)d_in[7];
    const float* bv    = (const float*)d_in[8];
    const float* wo    = (const float*)d_in[9];
    const float* bo    = (const float*)d_in[10];
    float* out = (float*)d_out;

    float *b2;
    float2* part;
    unsigned long long* rsum;
    fp16 *hnt, *qk, *v, *aot, *es, *wb;
    cudaGetSymbolAddress((void**)&hnt,  g_hnt);
    cudaGetSymbolAddress((void**)&qk,   g_qk);
    cudaGetSymbolAddress((void**)&v,    g_v);
    cudaGetSymbolAddress((void**)&aot,  g_aot);
    cudaGetSymbolAddress((void**)&es,   g_es);
    cudaGetSymbolAddress((void**)&wb,   g_wb);
    cudaGetSymbolAddress((void**)&b2,   g_b2);
    cudaGetSymbolAddress((void**)&part, g_part);
    cudaGetSymbolAddress((void**)&rsum, g_rsum);
    const fp16* wvb = wb + 2 * CH * CH;
    const fp16* wob = wb + 3 * CH * CH;

    const int SMEM = 2 * NST * SOP;   // 98304 B
    static int smem_set = 0;
    if (!smem_set) {
        cudaFuncSetAttribute(bgemm<1,1>, cudaFuncAttributeMaxDynamicSharedMemorySize, SMEM);
        cudaFuncSetAttribute(bgemm<2,1>, cudaFuncAttributeMaxDynamicSharedMemorySize, SMEM);
        cudaFuncSetAttribute(sgemm_exp,  cudaFuncAttributeMaxDynamicSharedMemorySize, SMEM);
        cudaFuncSetAttribute(bgemm<5,1>, cudaFuncAttributeMaxDynamicSharedMemorySize, SMEM);
        cudaFuncSetAttribute(bgemm<3,0>, cudaFuncAttributeMaxDynamicSharedMemorySize, SMEM);
        smem_set = 1;
    }

    const long long sCH  = (long long)CH * HW;
    const long long sQK  = (long long)HW * 2 * CH;
    const long long sHW  = (long long)HW * HW;
    // exp2 scale: (1/sqrt(512)) * log2(e)
    const float escale = 0.044194173824159216f * 1.4426950408889634f;

    // 0. zero rowsum accumulators
    cudaMemsetAsync(rsum, 0, BATCH * HW * sizeof(unsigned long long));
    // 1. weights -> fp16, bias concat
    prep_kernel<<<256, 256>>>(wq, wk, wv, wo, bq, bk, wb, b2);
    // 2. GroupNorm partial stats
    gn_stats_part<<<dim3(NG, 8, BATCH), 256>>>(x, part);
    // 3. fused apply + transpose -> hnt [HW, C] fp16
    gn_apply_transpose<<<dim3(HW / 32, CH / 32, BATCH), 256>>>(
        x, part, gamma, beta, hnt);

    // 4. qk = hnt . [Wq;Wk]^T + [bq;bk]              (M=4096, N=1024, K=512)
    bgemm<1,1><<<dim3(2 * CH / 128, HW / 128, BATCH), 128, SMEM>>>(
        hnt, wb, qk, b2, nullptr, CH, CH, CH, 2 * CH, sCH, 0, sQK, 1.f);
    // 5. v = Wv . hnt^T + bv                         (M=512, N=4096, K=512)
    bgemm<2,1><<<dim3(HW / 128, CH / 128, BATCH), 128, SMEM>>>(
        wvb, hnt, v, bv, nullptr, CH, CH, CH, HW, 0, sCH, sCH, 1.f);

    // 6. es = exp(q.k^T * scale), fp16-acc probe, rowsums in-epilogue
    sgemm_exp<<<dim3(HW / 128, HW / 128, BATCH), 128, SMEM>>>(
        qk, qk + CH, es, CH, 2 * CH, 2 * CH, HW, sQK, sQK, sHW, escale, rsum);

    // 7. ao_t = (es . v^T) / rowsum                  (M=4096, N=512, K=4096)
    bgemm<5,1><<<dim3(CH / 128, HW / 128, BATCH), 128, SMEM>>>(
        es, v, aot, (const float*)rsum, nullptr, HW, HW, HW, CH,
        sHW, sCH, sCH, 1.f);

    // 8. out = Wo . ao_t^T + bo + x                  (M=512, N=4096, K=512)
    bgemm<3,0><<<dim3(HW / 128, CH / 128, BATCH), 128, SMEM>>>(
        wob, aot, out, bo, x, CH, CH, CH, HW, 0, sCH, sCH, 1.f);
}